// round 6
// baseline (speedup 1.0000x reference)
#include <cuda_runtime.h>
#include <cuda_bf16.h>
#include <math.h>
#include <stdint.h>

#define SEQ   1024
#define MEMN  1024
#define TT    2048
#define BATCH 4
#define NH    16
#define DH    64
#define DM    1024
#define BH    (BATCH*NH)   // 64

// ---------------- scratch (device globals) ----------------
__device__ float g_ac[(size_t)BH*SEQ*TT];     // AC scores fp32
__device__ float g_bd[(size_t)BH*SEQ*TT];     // BD raw fp32

__device__ __nv_bfloat16 g_chi[(size_t)8192*1024];
__device__ __nv_bfloat16 g_clo[(size_t)8192*1024];
__device__ __nv_bfloat16 g_phi[(size_t)8192*1024];
__device__ __nv_bfloat16 g_plo[(size_t)8192*1024];
__device__ __nv_bfloat16 g_whi[(size_t)4096*1024];
__device__ __nv_bfloat16 g_wlo[(size_t)4096*1024];
__device__ __nv_bfloat16 g_wohi[(size_t)1024*1024];
__device__ __nv_bfloat16 g_wolo[(size_t)1024*1024];

__device__ __nv_bfloat16 g_quh[(size_t)BH*SEQ*DH], g_qul[(size_t)BH*SEQ*DH];
__device__ __nv_bfloat16 g_qvh[(size_t)BH*SEQ*DH], g_qvl[(size_t)BH*SEQ*DH];
__device__ __nv_bfloat16 g_kh [(size_t)BH*TT*DH],  g_kl [(size_t)BH*TT*DH];
__device__ __nv_bfloat16 g_vh [(size_t)BH*TT*DH],  g_vl [(size_t)BH*TT*DH];
__device__ __nv_bfloat16 g_rh [(size_t)BH*TT*DH],  g_rl [(size_t)BH*TT*DH];

__device__ __nv_bfloat16 g_ph[(size_t)BH*SEQ*TT];  // normalized probs (hi only)
__device__ __nv_bfloat16 g_avh[(size_t)SEQ*BATCH*DM], g_avl[(size_t)SEQ*BATCH*DM];

// ---------------- helpers ----------------
__device__ __forceinline__ uint32_t smem_u32(const void* p){
    uint32_t a;
    asm("{ .reg .u64 t; cvta.to.shared.u64 t, %1; cvt.u32.u64 %0, t; }" : "=r"(a) : "l"(p));
    return a;
}
__device__ __forceinline__ void cp16(uint32_t s, const void* g){
    asm volatile("cp.async.cg.shared.global [%0], [%1], 16;" :: "r"(s), "l"(g));
}
#define CP_COMMIT() asm volatile("cp.async.commit_group;" ::: "memory")
#define CP_WAIT0()  asm volatile("cp.async.wait_group 0;" ::: "memory")

__device__ __forceinline__ void ldm4(uint32_t* r, uint32_t addr){
    asm volatile("ldmatrix.sync.aligned.m8n8.x4.shared.b16 {%0,%1,%2,%3}, [%4];"
        : "=r"(r[0]), "=r"(r[1]), "=r"(r[2]), "=r"(r[3]) : "r"(addr));
}
__device__ __forceinline__ void ldm4t(uint32_t* r, uint32_t addr){
    asm volatile("ldmatrix.sync.aligned.m8n8.x4.trans.shared.b16 {%0,%1,%2,%3}, [%4];"
        : "=r"(r[0]), "=r"(r[1]), "=r"(r[2]), "=r"(r[3]) : "r"(addr));
}
__device__ __forceinline__ void mma_bf16(float* c, const uint32_t* a, uint32_t b0, uint32_t b1){
    asm volatile("mma.sync.aligned.m16n8k16.row.col.f32.bf16.bf16.f32 "
        "{%0,%1,%2,%3}, {%4,%5,%6,%7}, {%8,%9}, {%0,%1,%2,%3};"
        : "+f"(c[0]), "+f"(c[1]), "+f"(c[2]), "+f"(c[3])
        : "r"(a[0]), "r"(a[1]), "r"(a[2]), "r"(a[3]), "r"(b0), "r"(b1));
}
__device__ __forceinline__ void split8(const float* v, uint4& hi, uint4& lo){
    uint32_t hs[8], ls[8];
    #pragma unroll
    for (int i = 0; i < 8; i++){
        __nv_bfloat16 h = __float2bfloat16(v[i]);
        hs[i] = __bfloat16_as_ushort(h);
        ls[i] = __bfloat16_as_ushort(__float2bfloat16(v[i] - __bfloat162float(h)));
    }
    hi = make_uint4(hs[0]|(hs[1]<<16), hs[2]|(hs[3]<<16), hs[4]|(hs[5]<<16), hs[6]|(hs[7]<<16));
    lo = make_uint4(ls[0]|(ls[1]<<16), ls[2]|(ls[3]<<16), ls[4]|(ls[5]<<16), ls[6]|(ls[7]<<16));
}

__device__ __forceinline__ float warpReduceSum(float v){
    #pragma unroll
    for (int o = 16; o > 0; o >>= 1) v += __shfl_xor_sync(0xffffffffu, v, o);
    return v;
}
__device__ __forceinline__ float warpReduceMax(float v){
    #pragma unroll
    for (int o = 16; o > 0; o >>= 1) v = fmaxf(v, __shfl_xor_sync(0xffffffffu, v, o));
    return v;
}

// ---------------- kernel 0: fp32 -> bf16 hi/lo conversion ----------------
__global__ __launch_bounds__(256) void conv_kernel(
    const float* __restrict__ x, const float* __restrict__ mem,
    const float* __restrict__ pos, const float* __restrict__ Wqkv,
    const float* __restrict__ Wrel, const float* __restrict__ Wo)
{
    const size_t u = (size_t)blockIdx.x * 256 + threadIdx.x;
    const float* src;
    __nv_bfloat16 *dhi, *dlo;
    size_t elem;
    if (u < 2097152) {
        elem = u * 4;
        const size_t row = elem >> 10, col = elem & 1023;
        src = (row < 4096) ? (mem + row*1024 + col) : (x + (row-4096)*1024 + col);
        dhi = g_chi + elem; dlo = g_clo + elem;
    } else if (u < 4194304) {
        elem = (u - 2097152) * 4;
        src = pos + elem;
        dhi = g_phi + elem; dlo = g_plo + elem;
    } else if (u < 5242880) {
        elem = (u - 4194304) * 4;
        const size_t row = elem >> 10, col = elem & 1023;
        src = (row < 3072) ? (Wqkv + row*1024 + col) : (Wrel + (row-3072)*1024 + col);
        dhi = g_whi + elem; dlo = g_wlo + elem;
    } else {
        elem = (u - 5242880) * 4;
        src = Wo + elem;
        dhi = g_wohi + elem; dlo = g_wolo + elem;
    }
    float4 v = *(const float4*)src;
    float vv[4] = {v.x, v.y, v.z, v.w};
    uint32_t hs[4], ls[4];
    #pragma unroll
    for (int i = 0; i < 4; i++){
        __nv_bfloat16 h = __float2bfloat16(vv[i]);
        hs[i] = __bfloat16_as_ushort(h);
        ls[i] = __bfloat16_as_ushort(__float2bfloat16(vv[i] - __bfloat162float(h)));
    }
    *(uint2*)dhi = make_uint2(hs[0]|(hs[1]<<16), hs[2]|(hs[3]<<16));
    *(uint2*)dlo = make_uint2(ls[0]|(ls[1]<<16), ls[2]|(ls[3]<<16));
}

// ---------------- kernel 1: bf16-split projection GEMM ----------------
// Custom grid (1792 blocks): q-category tiles only cover m>=4096 (x rows).
#define PJ_BUF   40960
#define PJ_SMEM  (2*PJ_BUF)

__global__ __launch_bounds__(256) void proj_mma_kernel(
    const float* __restrict__ pbu, const float* __restrict__ pbv)
{
    extern __shared__ __align__(128) char smem[];
    const uint32_t sbase = smem_u32(smem);
    const int tid = threadIdx.x, lane = tid & 31, wid = tid >> 5;
    const int bid = blockIdx.x;
    int n0, m0;
    if (bid < 256){ n0 = (bid & 7) * 128; m0 = 4096 + (bid >> 3) * 128; }
    else { const int b2 = bid - 256; n0 = 1024 + (b2 % 24) * 128; m0 = (b2 / 24) * 128; }

    const bool is_rel = (n0 >= 3072);
    const __nv_bfloat16* Ahp = (is_rel ? g_phi : g_chi) + (size_t)m0 * 1024;
    const __nv_bfloat16* Alp = (is_rel ? g_plo : g_clo) + (size_t)m0 * 1024;
    const __nv_bfloat16* Bhp = g_whi + (size_t)n0 * 1024;
    const __nv_bfloat16* Blp = g_wlo + (size_t)n0 * 1024;

    const int wm = (wid & 3) * 32;
    const int wn = (wid >> 2) * 64;
    const int lsel = lane & 15;
    const int kof  = (lane < 16) ? 0 : 8;

    float acc[2][8][4];
    #pragma unroll
    for (int mt = 0; mt < 2; mt++)
        #pragma unroll
        for (int nt = 0; nt < 8; nt++)
            #pragma unroll
            for (int q = 0; q < 4; q++) acc[mt][nt][q] = 0.f;

    auto issue = [&](int c, int b){
        const int k0 = c * 32;
        const uint32_t sb = sbase + b * PJ_BUF;
        #pragma unroll
        for (int p = 0; p < 2; p++){
            const int u = p * 256 + tid;
            const int row = u >> 2, seg = u & 3;
            const size_t go = (size_t)row * 1024 + k0 + seg * 8;
            const uint32_t so = row * 80 + seg * 16;
            cp16(sb + so,          Ahp + go);
            cp16(sb + 10240 + so,  Alp + go);
            cp16(sb + 20480 + so,  Bhp + go);
            cp16(sb + 30720 + so,  Blp + go);
        }
        CP_COMMIT();
    };

    issue(0, 0);
    for (int c = 0; c < 32; c++){
        CP_WAIT0();
        __syncthreads();
        if (c + 1 < 32) issue(c + 1, (c + 1) & 1);
        const uint32_t sb = sbase + (c & 1) * PJ_BUF;
        #pragma unroll
        for (int kk = 0; kk < 32; kk += 16){
            uint32_t ah[2][4], al[2][4], bh[4][4], bl[4][4];
            #pragma unroll
            for (int mt = 0; mt < 2; mt++){
                const uint32_t ad = sb + (wm + mt*16 + lsel) * 80 + (kk + kof) * 2;
                ldm4(ah[mt], ad);
                ldm4(al[mt], ad + 10240);
            }
            #pragma unroll
            for (int g = 0; g < 4; g++){
                const uint32_t bd = sb + 20480 + (wn + g*16 + lsel) * 80 + (kk + kof) * 2;
                ldm4(bh[g], bd);
                ldm4(bl[g], bd + 10240);
            }
            #pragma unroll
            for (int mt = 0; mt < 2; mt++)
                #pragma unroll
                for (int nt = 0; nt < 8; nt++){
                    const int g = nt >> 1, s = nt & 1;
                    mma_bf16(acc[mt][nt], ah[mt], bh[g][s], bh[g][s+2]);
                    mma_bf16(acc[mt][nt], ah[mt], bl[g][s], bl[g][s+2]);
                    mma_bf16(acc[mt][nt], al[mt], bh[g][s], bh[g][s+2]);
                }
        }
    }

    __syncthreads();
    float* stg = (float*)smem;
    const int fr = lane >> 2, fc = (lane & 3) * 2;
    #pragma unroll
    for (int mt = 0; mt < 2; mt++)
        #pragma unroll
        for (int nt = 0; nt < 8; nt++){
            const int col = wn + nt*8 + fc;
            const int row0 = wm + mt*16 + fr;
            stg[row0*132 + col]       = acc[mt][nt][0];
            stg[row0*132 + col + 1]   = acc[mt][nt][1];
            stg[(row0+8)*132 + col]   = acc[mt][nt][2];
            stg[(row0+8)*132 + col+1] = acc[mt][nt][3];
        }
    __syncthreads();

    const int rr = tid >> 1, hf = tid & 1;
    const int m = m0 + rr;
    const int t_ = m >> 2, b_ = m & 3;
    const float* src = stg + rr * 132 + hf * 64;
    const int nbase = n0 + hf * 64;
    const int cat = n0 >> 10;
    if (cat == 0){
        const int i = t_ - MEMN;   // always >= 0 with new grid
        const int h = nbase >> 6;
        const size_t off = (((size_t)(b_*NH + h))*SEQ + i)*DH;
        #pragma unroll
        for (int s = 0; s < 8; s++){
            float qu8[8], qv8[8];
            #pragma unroll
            for (int e = 0; e < 8; e++){
                const float v = src[s*8 + e];
                qu8[e] = v + pbu[nbase + s*8 + e];
                qv8[e] = v + pbv[nbase + s*8 + e];
            }
            uint4 hi, lo;
            split8(qu8, hi, lo);
            *(uint4*)(g_quh + off + s*8) = hi;
            *(uint4*)(g_qul + off + s*8) = lo;
            split8(qv8, hi, lo);
            *(uint4*)(g_qvh + off + s*8) = hi;
            *(uint4*)(g_qvl + off + s*8) = lo;
        }
    } else {
        const int nn = nbase - cat*1024;
        const int h = nn >> 6;
        __nv_bfloat16* bh_ = (cat == 1) ? g_kh : (cat == 2) ? g_vh : g_rh;
        __nv_bfloat16* bl_ = (cat == 1) ? g_kl : (cat == 2) ? g_vl : g_rl;
        const size_t off = (((size_t)(b_*NH + h))*TT + t_)*DH;
        #pragma unroll
        for (int s = 0; s < 8; s++){
            uint4 hi, lo;
            split8(src + s*8, hi, lo);
            *(uint4*)(bh_ + off + s*8) = hi;
            *(uint4*)(bl_ + off + s*8) = lo;
        }
    }
}

// ---------------- kernel 2: bf16-split score GEMMs (K=64), chunked over bh ----------------
#define SC_SMEM 73728

__global__ __launch_bounds__(256) void score_mma_kernel(int bh0)
{
    extern __shared__ __align__(128) char smem[];
    const uint32_t sbase = smem_u32(smem);
    const int tid = threadIdx.x, lane = tid & 31, wid = tid >> 5;
    const int z = blockIdx.z;
    const int bh = bh0 + (z >> 1), which = z & 1;
    const __nv_bfloat16* Ahp = (which ? g_qvh : g_quh) + (size_t)bh * SEQ * DH;
    const __nv_bfloat16* Alp = (which ? g_qvl : g_qul) + (size_t)bh * SEQ * DH;
    const __nv_bfloat16* Bhp = (which ? g_rh  : g_kh ) + (size_t)bh * TT  * DH;
    const __nv_bfloat16* Blp = (which ? g_rl  : g_kl ) + (size_t)bh * TT  * DH;
    float* Ob = (which ? g_bd : g_ac) + (size_t)bh * SEQ * TT;
    const int i0 = blockIdx.y * 128;
    const int j0 = blockIdx.x * 128;

    const int wm = (wid & 3) * 32;
    const int wn = (wid >> 2) * 64;
    const int lsel = lane & 15;
    const int kof  = (lane < 16) ? 0 : 8;

    #pragma unroll
    for (int p = 0; p < 4; p++){
        const int u = p * 256 + tid;
        const int row = u >> 3, seg = u & 7;
        const uint32_t so = row * 144 + seg * 16;
        const size_t goA = (size_t)(i0 + row) * DH + seg * 8;
        const size_t goB = (size_t)(j0 + row) * DH + seg * 8;
        cp16(sbase + so,          Ahp + goA);
        cp16(sbase + 18432 + so,  Alp + goA);
        cp16(sbase + 36864 + so,  Bhp + goB);
        cp16(sbase + 55296 + so,  Blp + goB);
    }
    CP_COMMIT();

    float acc[2][8][4];
    #pragma unroll
    for (int mt = 0; mt < 2; mt++)
        #pragma unroll
        for (int nt = 0; nt < 8; nt++)
            #pragma unroll
            for (int q = 0; q < 4; q++) acc[mt][nt][q] = 0.f;

    CP_WAIT0();
    __syncthreads();

    #pragma unroll
    for (int kk = 0; kk < 64; kk += 16){
        uint32_t ah[2][4], al[2][4], bh[4][4], bl[4][4];
        #pragma unroll
        for (int mt = 0; mt < 2; mt++){
            const uint32_t ad = sbase + (wm + mt*16 + lsel) * 144 + (kk + kof) * 2;
            ldm4(ah[mt], ad);
            ldm4(al[mt], ad + 18432);
        }
        #pragma unroll
        for (int g = 0; g < 4; g++){
            const uint32_t bd = sbase + 36864 + (wn + g*16 + lsel) * 144 + (kk + kof) * 2;
            ldm4(bh[g], bd);
            ldm4(bl[g], bd + 18432);
        }
        #pragma unroll
        for (int mt = 0; mt < 2; mt++)
            #pragma unroll
            for (int nt = 0; nt < 8; nt++){
                const int g = nt >> 1, s = nt & 1;
                mma_bf16(acc[mt][nt], ah[mt], bh[g][s], bh[g][s+2]);
                mma_bf16(acc[mt][nt], ah[mt], bl[g][s], bl[g][s+2]);
                mma_bf16(acc[mt][nt], al[mt], bh[g][s], bh[g][s+2]);
            }
    }

    __syncthreads();
    float* stg = (float*)smem;
    const int fr = lane >> 2, fc = (lane & 3) * 2;
    #pragma unroll
    for (int mt = 0; mt < 2; mt++)
        #pragma unroll
        for (int nt = 0; nt < 8; nt++){
            const int col = wn + nt*8 + fc;
            const int row0 = wm + mt*16 + fr;
            stg[row0*132 + col]       = acc[mt][nt][0];
            stg[row0*132 + col + 1]   = acc[mt][nt][1];
            stg[(row0+8)*132 + col]   = acc[mt][nt][2];
            stg[(row0+8)*132 + col+1] = acc[mt][nt][3];
        }
    __syncthreads();
    const int rr = tid >> 1, hf = tid & 1;
    const float* src = stg + rr * 132 + hf * 64;
    float* orow = Ob + (size_t)(i0 + rr) * TT + j0 + hf * 64;
    #pragma unroll
    for (int s = 0; s < 16; s++)
        *(float4*)(orow + s*4) = *(const float4*)(src + s*4);
}

// ---------------- kernel 3: rel-shift + softmax -> normalized bf16 probs ----------------
__global__ __launch_bounds__(256) void softmax_shift_kernel(int bh0)
{
    const int i  = blockIdx.x;
    const int bh = bh0 + blockIdx.y;
    const int t  = threadIdx.x;
    const size_t rowoff = ((size_t)bh*SEQ + i) * TT;
    const float* ac = g_ac + rowoff;
    const float* bd0 = g_bd + rowoff;
    const float* bd1 = bd0 + TT;

    float sv[8];
    float lmax = -INFINITY;
    #pragma unroll
    for (int q = 0; q < 8; q++){
        const int j = q*256 + t;
        const int delta = j - i;
        float bd;
        if (delta <= 1024)      bd = bd0[delta + 1023];
        else if (delta == 1025) bd = 0.f;
        else                    bd = bd1[delta - 1026];
        const float s = (ac[j] + bd) * 0.125f;
        sv[q] = s;
        lmax = fmaxf(lmax, s);
    }
    __shared__ float sh[8];
    float wmax = warpReduceMax(lmax);
    if ((t & 31) == 0) sh[t >> 5] = wmax;
    __syncthreads();
    float mx = sh[0];
    #pragma unroll
    for (int w = 1; w < 8; w++) mx = fmaxf(mx, sh[w]);
    __syncthreads();

    float lsum = 0.f;
    #pragma unroll
    for (int q = 0; q < 8; q++){
        const float p = __expf(sv[q] - mx);
        sv[q] = p;
        lsum += p;
    }
    float wsum = warpReduceSum(lsum);
    if ((t & 31) == 0) sh[t >> 5] = wsum;
    __syncthreads();
    float sum = 0.f;
    #pragma unroll
    for (int w = 0; w < 8; w++) sum += sh[w];
    const float sinv = 1.f / sum;

    __nv_bfloat16* ph = g_ph + rowoff;
    #pragma unroll
    for (int q = 0; q < 8; q++){
        const int j = q*256 + t;
        ph[j] = __float2bfloat16(sv[q] * sinv);
    }
}

// ---------------- kernel 4: PV GEMM (P hi-only x V hi/lo) ----------------
#define PV_BUF   19456
#define PV_SMEM  (2*PV_BUF)

__global__ __launch_bounds__(256) void pv_mma_kernel(int bh0)
{
    extern __shared__ __align__(128) char smem[];
    const uint32_t sbase = smem_u32(smem);
    const int tid = threadIdx.x, lane = tid & 31, wid = tid >> 5;
    const int bh = bh0 + blockIdx.y;
    const int i0 = blockIdx.x * 128;
    const __nv_bfloat16* Php = g_ph + (size_t)bh*SEQ*TT + (size_t)i0*TT;
    const __nv_bfloat16* Vhp = g_vh + (size_t)bh*TT*DH;
    const __nv_bfloat16* Vlp = g_vl + (size_t)bh*TT*DH;

    const int wm = (wid & 3) * 32;
    const int wn = (wid >> 2) * 32;
    const int lsel = lane & 15;
    const int kof  = (lane < 16) ? 0 : 8;
    const int tcol = (lane >> 4) * 8;

    float acc[2][4][4];
    #pragma unroll
    for (int mt = 0; mt < 2; mt++)
        #pragma unroll
        for (int nt = 0; nt < 4; nt++)
            #pragma unroll
            for (int q = 0; q < 4; q++) acc[mt][nt][q] = 0.f;

    auto issue = [&](int c, int b){
        const int k0 = c * 32;
        const uint32_t sb = sbase + b * PV_BUF;
        #pragma unroll
        for (int p = 0; p < 2; p++){
            const int u = p * 256 + tid;
            const int row = u >> 2, seg = u & 3;
            const size_t go = (size_t)row * TT + k0 + seg * 8;
            cp16(sb + row * 80 + seg * 16, Php + go);
        }
        {
            const int row = tid >> 3, seg = tid & 7;
            const size_t go = (size_t)(k0 + row) * DH + seg * 8;
            const uint32_t so = row * 144 + seg * 16;
            cp16(sb + 10240 + so, Vhp + go);
            cp16(sb + 14848 + so, Vlp + go);
        }
        CP_COMMIT();
    };

    issue(0, 0);
    for (int c = 0; c < 64; c++){
        CP_WAIT0();
        __syncthreads();
        if (c + 1 < 64) issue(c + 1, (c + 1) & 1);
        const uint32_t sb = sbase + (c & 1) * PV_BUF;
        #pragma unroll
        for (int kk = 0; kk < 32; kk += 16){
            uint32_t ph[2][4], vh[2][4], vl[2][4];
            #pragma unroll
            for (int mt = 0; mt < 2; mt++){
                const uint32_t ad = sb + (wm + mt*16 + lsel) * 80 + (kk + kof) * 2;
                ldm4(ph[mt], ad);
            }
            #pragma unroll
            for (int g = 0; g < 2; g++){
                const uint32_t bd = sb + 10240 + (kk + lsel) * 144 + (wn + g*16 + tcol) * 2;
                ldm4t(vh[g], bd);
                ldm4t(vl[g], bd + 4608);
            }
            #pragma unroll
            for (int mt = 0; mt < 2; mt++)
                #pragma unroll
                for (int nt = 0; nt < 4; nt++){
                    const int g = nt >> 1, s = nt & 1;
                    mma_bf16(acc[mt][nt], ph[mt], vh[g][2*s], vh[g][2*s+1]);
                    mma_bf16(acc[mt][nt], ph[mt], vl[g][2*s], vl[g][2*s+1]);
                }
        }
    }

    __syncthreads();
    float* stg = (float*)smem;
    const int fr = lane >> 2, fc = (lane & 3) * 2;
    #pragma unroll
    for (int mt = 0; mt < 2; mt++)
        #pragma unroll
        for (int nt = 0; nt < 4; nt++){
            const int col = wn + nt*8 + fc;
            const int row0 = wm + mt*16 + fr;
            stg[row0*68 + col]       = acc[mt][nt][0];
            stg[row0*68 + col + 1]   = acc[mt][nt][1];
            stg[(row0+8)*68 + col]   = acc[mt][nt][2];
            stg[(row0+8)*68 + col+1] = acc[mt][nt][3];
        }
    __syncthreads();
    const int rr = tid >> 1, hf = tid & 1;
    const int b = bh >> 4, h = bh & 15;
    const int i = i0 + rr;
    const float* src = stg + rr * 68 + hf * 32;
    const size_t off = ((size_t)i*BATCH + b)*DM + h*DH + hf*32;
    #pragma unroll
    for (int s = 0; s < 4; s++){
        uint4 hi, lo;
        split8(src + s*8, hi, lo);
        *(uint4*)(g_avh + off + s*8) = hi;
        *(uint4*)(g_avl + off + s*8) = lo;
    }
}

// ---------------- kernel 5: bf16-split out projection + residual ----------------
__global__ __launch_bounds__(256) void outproj_mma_kernel(const float* __restrict__ x,
                                                          float* __restrict__ out)
{
    extern __shared__ __align__(128) char smem[];
    const uint32_t sbase = smem_u32(smem);
    const int tid = threadIdx.x, lane = tid & 31, wid = tid >> 5;
    const int n0 = blockIdx.x * 128;
    const int m0 = blockIdx.y * 128;
    const __nv_bfloat16* Ahp = g_avh + (size_t)m0 * 1024;
    const __nv_bfloat16* Alp = g_avl + (size_t)m0 * 1024;
    const __nv_bfloat16* Bhp = g_wohi + (size_t)n0 * 1024;
    const __nv_bfloat16* Blp = g_wolo + (size_t)n0 * 1024;

    const int wm = (wid & 3) * 32;
    const int wn = (wid >> 2) * 64;
    const int lsel = lane & 15;
    const int kof  = (lane < 16) ? 0 : 8;

    float acc[2][8][4];
    #pragma unroll
    for (int mt = 0; mt < 2; mt++)
        #pragma unroll
        for (int nt = 0; nt < 8; nt++)
            #pragma unroll
            for (int q = 0; q < 4; q++) acc[mt][nt][q] = 0.f;

    auto issue = [&](int c, int b){
        const int k0 = c * 32;
        const uint32_t sb = sbase + b * PJ_BUF;
        #pragma unroll
        for (int p = 0; p < 2; p++){
            const int u = p * 256 + tid;
            const int row = u >> 2, seg = u & 3;
            const size_t go = (size_t)row * 1024 + k0 + seg * 8;
            const uint32_t so = row * 80 + seg * 16;
            cp16(sb + so,          Ahp + go);
            cp16(sb + 10240 + so,  Alp + go);
            cp16(sb + 20480 + so,  Bhp + go);
            cp16(sb + 30720 + so,  Blp + go);
        }
        CP_COMMIT();
    };

    issue(0, 0);
    for (int c = 0; c < 32; c++){
        CP_WAIT0();
        __syncthreads();
        if (c + 1 < 32) issue(c + 1, (c + 1) & 1);
        const uint32_t sb = sbase + (c & 1) * PJ_BUF;
        #pragma unroll
        for (int kk = 0; kk < 32; kk += 16){
            uint32_t ah[2][4], al[2][4], bh[4][4], bl[4][4];
            #pragma unroll
            for (int mt = 0; mt < 2; mt++){
                const uint32_t ad = sb + (wm + mt*16 + lsel) * 80 + (kk + kof) * 2;
                ldm4(ah[mt], ad);
                ldm4(al[mt], ad + 10240);
            }
            #pragma unroll
            for (int g = 0; g < 4; g++){
                const uint32_t bd = sb + 20480 + (wn + g*16 + lsel) * 80 + (kk + kof) * 2;
                ldm4(bh[g], bd);
                ldm4(bl[g], bd + 10240);
            }
            #pragma unroll
            for (int mt = 0; mt < 2; mt++)
                #pragma unroll
                for (int nt = 0; nt < 8; nt++){
                    const int g = nt >> 1, s = nt & 1;
                    mma_bf16(acc[mt][nt], ah[mt], bh[g][s], bh[g][s+2]);
                    mma_bf16(acc[mt][nt], ah[mt], bl[g][s], bl[g][s+2]);
                    mma_bf16(acc[mt][nt], al[mt], bh[g][s], bh[g][s+2]);
                }
        }
    }

    __syncthreads();
    float* stg = (float*)smem;
    const int fr = lane >> 2, fc = (lane & 3) * 2;
    #pragma unroll
    for (int mt = 0; mt < 2; mt++)
        #pragma unroll
        for (int nt = 0; nt < 8; nt++){
            const int col = wn + nt*8 + fc;
            const int row0 = wm + mt*16 + fr;
            stg[row0*132 + col]       = acc[mt][nt][0];
            stg[row0*132 + col + 1]   = acc[mt][nt][1];
            stg[(row0+8)*132 + col]   = acc[mt][nt][2];
            stg[(row0+8)*132 + col+1] = acc[mt][nt][3];
        }
    __syncthreads();
    const int rr = tid >> 1, hf = tid & 1;
    const int m = m0 + rr;
    const float* src = stg + rr * 132 + hf * 64;
    const float* xr = x + (size_t)m*DM + n0 + hf*64;
    float* orow = out + (size_t)m*DM + n0 + hf*64;
    #pragma unroll
    for (int s = 0; s < 16; s++){
        float4 v = *(const float4*)(src + s*4);
        float4 xx = *(const float4*)(xr + s*4);
        *(float4*)(orow + s*4) = make_float4(v.x+xx.x, v.y+xx.y, v.z+xx.z, v.w+xx.w);
    }
}

// ---------------- kernel 6: LayerNorm ----------------
__global__ __launch_bounds__(256) void ln_kernel(float* __restrict__ out,
                                                 const float* __restrict__ gamma,
                                                 const float* __restrict__ beta)
{
    const int row = blockIdx.x;
    float* y = out + (size_t)row * DM;
    const int t = threadIdx.x;
    float v[4];
    float s = 0.f, sq = 0.f;
    #pragma unroll
    for (int q = 0; q < 4; q++){
        v[q] = y[q*256 + t];
        s += v[q];
        sq += v[q]*v[q];
    }
    __shared__ float sh[16];
    float ws = warpReduceSum(s);
    float wq = warpReduceSum(sq);
    if ((t & 31) == 0){ sh[t>>5] = ws; sh[8 + (t>>5)] = wq; }
    __syncthreads();
    s = 0.f; sq = 0.f;
    #pragma unroll
    for (int w = 0; w < 8; w++){ s += sh[w]; sq += sh[8+w]; }
    const float mu = s * (1.f/1024.f);
    const float var = sq * (1.f/1024.f) - mu*mu;
    const float rstd = rsqrtf(var + 1e-5f);
    #pragma unroll
    for (int q = 0; q < 4; q++){
        const int d = q*256 + t;
        y[d] = gamma[d] * ((v[q] - mu) * rstd) + beta[d];
    }
}

// ---------------- launch ----------------
#define NCHUNK 4
#define CHBH   16

extern "C" void kernel_launch(void* const* d_in, const int* in_sizes, int n_in,
                              void* d_out, int out_size)
{
    const float* x     = (const float*)d_in[0];
    const float* mem   = (const float*)d_in[1];
    const float* pos   = (const float*)d_in[2];
    const float* pbu   = (const float*)d_in[3];
    const float* pbv   = (const float*)d_in[4];
    const float* Wqkv  = (const float*)d_in[5];
    const float* Wrel  = (const float*)d_in[6];
    const float* Wo    = (const float*)d_in[7];
    const float* gamma = (const float*)d_in[8];
    const float* beta  = (const float*)d_in[9];
    float* out = (float*)d_out;

    static cudaStream_t s1 = nullptr;
    static cudaEvent_t evS[NCHUNK], evM[NCHUNK];
    if (!s1){
        cudaStreamCreateWithFlags(&s1, cudaStreamNonBlocking);
        for (int c = 0; c < NCHUNK; c++){
            cudaEventCreateWithFlags(&evS[c], cudaEventDisableTiming);
            cudaEventCreateWithFlags(&evM[c], cudaEventDisableTiming);
        }
        cudaFuncSetAttribute(proj_mma_kernel,    cudaFuncAttributeMaxDynamicSharedMemorySize, PJ_SMEM);
        cudaFuncSetAttribute(score_mma_kernel,   cudaFuncAttributeMaxDynamicSharedMemorySize, SC_SMEM);
        cudaFuncSetAttribute(pv_mma_kernel,      cudaFuncAttributeMaxDynamicSharedMemorySize, PV_SMEM);
        cudaFuncSetAttribute(outproj_mma_kernel, cudaFuncAttributeMaxDynamicSharedMemorySize, PJ_SMEM);
    }

    conv_kernel<<<21504, 256>>>(x, mem, pos, Wqkv, Wrel, Wo);
    proj_mma_kernel<<<1792, 256, PJ_SMEM>>>(pbu, pbv);

    for (int c = 0; c < NCHUNK; c++){
        score_mma_kernel<<<dim3(16, 8, 2*CHBH), 256, SC_SMEM>>>(c * CHBH);
        cudaEventRecord(evS[c], 0);
        cudaStreamWaitEvent(s1, evS[c], 0);
        softmax_shift_kernel<<<dim3(1024, CHBH), 256, 0, s1>>>(c * CHBH);
        cudaEventRecord(evM[c], s1);
    }
    for (int c = 0; c < NCHUNK; c++){
        cudaStreamWaitEvent(0, evM[c], 0);
        pv_mma_kernel<<<dim3(8, CHBH), 256, PV_SMEM>>>(c * CHBH);
    }
    outproj_mma_kernel<<<dim3(8, 32), 256, PJ_SMEM>>>(x, out);
    ln_kernel<<<4096, 256>>>(out, gamma, beta);
}

// round 7
// speedup vs baseline: 1.0589x; 1.0589x over previous
#include <cuda_runtime.h>
#include <cuda_bf16.h>
#include <math.h>
#include <stdint.h>

#define SEQ   1024
#define MEMN  1024
#define TT    2048
#define BATCH 4
#define NH    16
#define DH    64
#define DM    1024
#define BH    (BATCH*NH)   // 64

// ---------------- scratch (device globals) ----------------
__device__ float g_ac[(size_t)BH*SEQ*TT];     // AC scores fp32
__device__ float g_bd[(size_t)BH*SEQ*TT];     // BD raw fp32

__device__ __nv_bfloat16 g_chi[(size_t)8192*1024];
__device__ __nv_bfloat16 g_clo[(size_t)8192*1024];
__device__ __nv_bfloat16 g_phi[(size_t)8192*1024];
__device__ __nv_bfloat16 g_plo[(size_t)8192*1024];
__device__ __nv_bfloat16 g_whi[(size_t)4096*1024];
__device__ __nv_bfloat16 g_wlo[(size_t)4096*1024];
__device__ __nv_bfloat16 g_wohi[(size_t)1024*1024];
__device__ __nv_bfloat16 g_wolo[(size_t)1024*1024];

__device__ __nv_bfloat16 g_quh[(size_t)BH*SEQ*DH], g_qul[(size_t)BH*SEQ*DH];
__device__ __nv_bfloat16 g_qvh[(size_t)BH*SEQ*DH], g_qvl[(size_t)BH*SEQ*DH];
__device__ __nv_bfloat16 g_kh [(size_t)BH*TT*DH],  g_kl [(size_t)BH*TT*DH];
__device__ __nv_bfloat16 g_vh [(size_t)BH*TT*DH],  g_vl [(size_t)BH*TT*DH];
__device__ __nv_bfloat16 g_rh [(size_t)BH*TT*DH],  g_rl [(size_t)BH*TT*DH];

__device__ __nv_bfloat16 g_ph[(size_t)BH*SEQ*TT];  // normalized probs (hi only)
__device__ __nv_bfloat16 g_avh[(size_t)SEQ*BATCH*DM], g_avl[(size_t)SEQ*BATCH*DM];

// ---------------- helpers ----------------
__device__ __forceinline__ uint32_t smem_u32(const void* p){
    uint32_t a;
    asm("{ .reg .u64 t; cvta.to.shared.u64 t, %1; cvt.u32.u64 %0, t; }" : "=r"(a) : "l"(p));
    return a;
}
__device__ __forceinline__ void cp16(uint32_t s, const void* g){
    asm volatile("cp.async.cg.shared.global [%0], [%1], 16;" :: "r"(s), "l"(g));
}
#define CP_COMMIT() asm volatile("cp.async.commit_group;" ::: "memory")
#define CP_WAIT0()  asm volatile("cp.async.wait_group 0;" ::: "memory")

__device__ __forceinline__ void ldm4(uint32_t* r, uint32_t addr){
    asm volatile("ldmatrix.sync.aligned.m8n8.x4.shared.b16 {%0,%1,%2,%3}, [%4];"
        : "=r"(r[0]), "=r"(r[1]), "=r"(r[2]), "=r"(r[3]) : "r"(addr));
}
__device__ __forceinline__ void ldm4t(uint32_t* r, uint32_t addr){
    asm volatile("ldmatrix.sync.aligned.m8n8.x4.trans.shared.b16 {%0,%1,%2,%3}, [%4];"
        : "=r"(r[0]), "=r"(r[1]), "=r"(r[2]), "=r"(r[3]) : "r"(addr));
}
__device__ __forceinline__ void mma_bf16(float* c, const uint32_t* a, uint32_t b0, uint32_t b1){
    asm volatile("mma.sync.aligned.m16n8k16.row.col.f32.bf16.bf16.f32 "
        "{%0,%1,%2,%3}, {%4,%5,%6,%7}, {%8,%9}, {%0,%1,%2,%3};"
        : "+f"(c[0]), "+f"(c[1]), "+f"(c[2]), "+f"(c[3])
        : "r"(a[0]), "r"(a[1]), "r"(a[2]), "r"(a[3]), "r"(b0), "r"(b1));
}
__device__ __forceinline__ void split8(const float* v, uint4& hi, uint4& lo){
    uint32_t hs[8], ls[8];
    #pragma unroll
    for (int i = 0; i < 8; i++){
        __nv_bfloat16 h = __float2bfloat16(v[i]);
        hs[i] = __bfloat16_as_ushort(h);
        ls[i] = __bfloat16_as_ushort(__float2bfloat16(v[i] - __bfloat162float(h)));
    }
    hi = make_uint4(hs[0]|(hs[1]<<16), hs[2]|(hs[3]<<16), hs[4]|(hs[5]<<16), hs[6]|(hs[7]<<16));
    lo = make_uint4(ls[0]|(ls[1]<<16), ls[2]|(ls[3]<<16), ls[4]|(ls[5]<<16), ls[6]|(ls[7]<<16));
}

__device__ __forceinline__ float warpReduceSum(float v){
    #pragma unroll
    for (int o = 16; o > 0; o >>= 1) v += __shfl_xor_sync(0xffffffffu, v, o);
    return v;
}
__device__ __forceinline__ float warpReduceMax(float v){
    #pragma unroll
    for (int o = 16; o > 0; o >>= 1) v = fmaxf(v, __shfl_xor_sync(0xffffffffu, v, o));
    return v;
}

// ---------------- kernel 0: fp32 -> bf16 hi/lo conversion ----------------
__global__ __launch_bounds__(256) void conv_kernel(
    const float* __restrict__ x, const float* __restrict__ mem,
    const float* __restrict__ pos, const float* __restrict__ Wqkv,
    const float* __restrict__ Wrel, const float* __restrict__ Wo)
{
    const size_t u = (size_t)blockIdx.x * 256 + threadIdx.x;
    const float* src;
    __nv_bfloat16 *dhi, *dlo;
    size_t elem;
    if (u < 2097152) {
        elem = u * 4;
        const size_t row = elem >> 10, col = elem & 1023;
        src = (row < 4096) ? (mem + row*1024 + col) : (x + (row-4096)*1024 + col);
        dhi = g_chi + elem; dlo = g_clo + elem;
    } else if (u < 4194304) {
        elem = (u - 2097152) * 4;
        src = pos + elem;
        dhi = g_phi + elem; dlo = g_plo + elem;
    } else if (u < 5242880) {
        elem = (u - 4194304) * 4;
        const size_t row = elem >> 10, col = elem & 1023;
        src = (row < 3072) ? (Wqkv + row*1024 + col) : (Wrel + (row-3072)*1024 + col);
        dhi = g_whi + elem; dlo = g_wlo + elem;
    } else {
        elem = (u - 5242880) * 4;
        src = Wo + elem;
        dhi = g_wohi + elem; dlo = g_wolo + elem;
    }
    float4 v = *(const float4*)src;
    float vv[4] = {v.x, v.y, v.z, v.w};
    uint32_t hs[4], ls[4];
    #pragma unroll
    for (int i = 0; i < 4; i++){
        __nv_bfloat16 h = __float2bfloat16(vv[i]);
        hs[i] = __bfloat16_as_ushort(h);
        ls[i] = __bfloat16_as_ushort(__float2bfloat16(vv[i] - __bfloat162float(h)));
    }
    *(uint2*)dhi = make_uint2(hs[0]|(hs[1]<<16), hs[2]|(hs[3]<<16));
    *(uint2*)dlo = make_uint2(ls[0]|(ls[1]<<16), ls[2]|(ls[3]<<16));
}

// ---------------- kernel 1: bf16-split projection GEMM ----------------
#define PJ_BUF   40960
#define PJ_SMEM  (2*PJ_BUF)

__global__ __launch_bounds__(256) void proj_mma_kernel(
    const float* __restrict__ pbu, const float* __restrict__ pbv)
{
    extern __shared__ __align__(128) char smem[];
    const uint32_t sbase = smem_u32(smem);
    const int tid = threadIdx.x, lane = tid & 31, wid = tid >> 5;
    const int bid = blockIdx.x;
    int n0, m0;
    if (bid < 256){ n0 = (bid & 7) * 128; m0 = 4096 + (bid >> 3) * 128; }
    else { const int b2 = bid - 256; n0 = 1024 + (b2 % 24) * 128; m0 = (b2 / 24) * 128; }

    const bool is_rel = (n0 >= 3072);
    const __nv_bfloat16* Ahp = (is_rel ? g_phi : g_chi) + (size_t)m0 * 1024;
    const __nv_bfloat16* Alp = (is_rel ? g_plo : g_clo) + (size_t)m0 * 1024;
    const __nv_bfloat16* Bhp = g_whi + (size_t)n0 * 1024;
    const __nv_bfloat16* Blp = g_wlo + (size_t)n0 * 1024;

    const int wm = (wid & 3) * 32;
    const int wn = (wid >> 2) * 64;
    const int lsel = lane & 15;
    const int kof  = (lane < 16) ? 0 : 8;

    float acc[2][8][4];
    #pragma unroll
    for (int mt = 0; mt < 2; mt++)
        #pragma unroll
        for (int nt = 0; nt < 8; nt++)
            #pragma unroll
            for (int q = 0; q < 4; q++) acc[mt][nt][q] = 0.f;

    auto issue = [&](int c, int b){
        const int k0 = c * 32;
        const uint32_t sb = sbase + b * PJ_BUF;
        #pragma unroll
        for (int p = 0; p < 2; p++){
            const int u = p * 256 + tid;
            const int row = u >> 2, seg = u & 3;
            const size_t go = (size_t)row * 1024 + k0 + seg * 8;
            const uint32_t so = row * 80 + seg * 16;
            cp16(sb + so,          Ahp + go);
            cp16(sb + 10240 + so,  Alp + go);
            cp16(sb + 20480 + so,  Bhp + go);
            cp16(sb + 30720 + so,  Blp + go);
        }
        CP_COMMIT();
    };

    issue(0, 0);
    for (int c = 0; c < 32; c++){
        CP_WAIT0();
        __syncthreads();
        if (c + 1 < 32) issue(c + 1, (c + 1) & 1);
        const uint32_t sb = sbase + (c & 1) * PJ_BUF;
        #pragma unroll
        for (int kk = 0; kk < 32; kk += 16){
            uint32_t ah[2][4], al[2][4], bh[4][4], bl[4][4];
            #pragma unroll
            for (int mt = 0; mt < 2; mt++){
                const uint32_t ad = sb + (wm + mt*16 + lsel) * 80 + (kk + kof) * 2;
                ldm4(ah[mt], ad);
                ldm4(al[mt], ad + 10240);
            }
            #pragma unroll
            for (int g = 0; g < 4; g++){
                const uint32_t bd = sb + 20480 + (wn + g*16 + lsel) * 80 + (kk + kof) * 2;
                ldm4(bh[g], bd);
                ldm4(bl[g], bd + 10240);
            }
            #pragma unroll
            for (int mt = 0; mt < 2; mt++)
                #pragma unroll
                for (int nt = 0; nt < 8; nt++){
                    const int g = nt >> 1, s = nt & 1;
                    mma_bf16(acc[mt][nt], ah[mt], bh[g][s], bh[g][s+2]);
                    mma_bf16(acc[mt][nt], ah[mt], bl[g][s], bl[g][s+2]);
                    mma_bf16(acc[mt][nt], al[mt], bh[g][s], bh[g][s+2]);
                }
        }
    }

    __syncthreads();
    float* stg = (float*)smem;
    const int fr = lane >> 2, fc = (lane & 3) * 2;
    #pragma unroll
    for (int mt = 0; mt < 2; mt++)
        #pragma unroll
        for (int nt = 0; nt < 8; nt++){
            const int col = wn + nt*8 + fc;
            const int row0 = wm + mt*16 + fr;
            stg[row0*132 + col]       = acc[mt][nt][0];
            stg[row0*132 + col + 1]   = acc[mt][nt][1];
            stg[(row0+8)*132 + col]   = acc[mt][nt][2];
            stg[(row0+8)*132 + col+1] = acc[mt][nt][3];
        }
    __syncthreads();

    const int rr = tid >> 1, hf = tid & 1;
    const int m = m0 + rr;
    const int t_ = m >> 2, b_ = m & 3;
    const float* src = stg + rr * 132 + hf * 64;
    const int nbase = n0 + hf * 64;
    const int cat = n0 >> 10;
    if (cat == 0){
        const int i = t_ - MEMN;
        const int h = nbase >> 6;
        const size_t off = (((size_t)(b_*NH + h))*SEQ + i)*DH;
        #pragma unroll
        for (int s = 0; s < 8; s++){
            float qu8[8], qv8[8];
            #pragma unroll
            for (int e = 0; e < 8; e++){
                const float v = src[s*8 + e];
                qu8[e] = v + pbu[nbase + s*8 + e];
                qv8[e] = v + pbv[nbase + s*8 + e];
            }
            uint4 hi, lo;
            split8(qu8, hi, lo);
            *(uint4*)(g_quh + off + s*8) = hi;
            *(uint4*)(g_qul + off + s*8) = lo;
            split8(qv8, hi, lo);
            *(uint4*)(g_qvh + off + s*8) = hi;
            *(uint4*)(g_qvl + off + s*8) = lo;
        }
    } else {
        const int nn = nbase - cat*1024;
        const int h = nn >> 6;
        __nv_bfloat16* bh_ = (cat == 1) ? g_kh : (cat == 2) ? g_vh : g_rh;
        __nv_bfloat16* bl_ = (cat == 1) ? g_kl : (cat == 2) ? g_vl : g_rl;
        const size_t off = (((size_t)(b_*NH + h))*TT + t_)*DH;
        #pragma unroll
        for (int s = 0; s < 8; s++){
            uint4 hi, lo;
            split8(src + s*8, hi, lo);
            *(uint4*)(bh_ + off + s*8) = hi;
            *(uint4*)(bl_ + off + s*8) = lo;
        }
    }
}

// ---------------- kernel 2: bf16-split score GEMMs (K=64), chunked over bh ----------------
#define SC_SMEM 73728

__global__ __launch_bounds__(256) void score_mma_kernel(int bh0)
{
    extern __shared__ __align__(128) char smem[];
    const uint32_t sbase = smem_u32(smem);
    const int tid = threadIdx.x, lane = tid & 31, wid = tid >> 5;
    const int z = blockIdx.z;
    const int bh = bh0 + (z >> 1), which = z & 1;
    const __nv_bfloat16* Ahp = (which ? g_qvh : g_quh) + (size_t)bh * SEQ * DH;
    const __nv_bfloat16* Alp = (which ? g_qvl : g_qul) + (size_t)bh * SEQ * DH;
    const __nv_bfloat16* Bhp = (which ? g_rh  : g_kh ) + (size_t)bh * TT  * DH;
    const __nv_bfloat16* Blp = (which ? g_rl  : g_kl ) + (size_t)bh * TT  * DH;
    float* Ob = (which ? g_bd : g_ac) + (size_t)bh * SEQ * TT;
    const int i0 = blockIdx.y * 128;
    const int j0 = blockIdx.x * 128;

    const int wm = (wid & 3) * 32;
    const int wn = (wid >> 2) * 64;
    const int lsel = lane & 15;
    const int kof  = (lane < 16) ? 0 : 8;

    #pragma unroll
    for (int p = 0; p < 4; p++){
        const int u = p * 256 + tid;
        const int row = u >> 3, seg = u & 7;
        const uint32_t so = row * 144 + seg * 16;
        const size_t goA = (size_t)(i0 + row) * DH + seg * 8;
        const size_t goB = (size_t)(j0 + row) * DH + seg * 8;
        cp16(sbase + so,          Ahp + goA);
        cp16(sbase + 18432 + so,  Alp + goA);
        cp16(sbase + 36864 + so,  Bhp + goB);
        cp16(sbase + 55296 + so,  Blp + goB);
    }
    CP_COMMIT();

    float acc[2][8][4];
    #pragma unroll
    for (int mt = 0; mt < 2; mt++)
        #pragma unroll
        for (int nt = 0; nt < 8; nt++)
            #pragma unroll
            for (int q = 0; q < 4; q++) acc[mt][nt][q] = 0.f;

    CP_WAIT0();
    __syncthreads();

    #pragma unroll
    for (int kk = 0; kk < 64; kk += 16){
        uint32_t ah[2][4], al[2][4], bh[4][4], bl[4][4];
        #pragma unroll
        for (int mt = 0; mt < 2; mt++){
            const uint32_t ad = sbase + (wm + mt*16 + lsel) * 144 + (kk + kof) * 2;
            ldm4(ah[mt], ad);
            ldm4(al[mt], ad + 18432);
        }
        #pragma unroll
        for (int g = 0; g < 4; g++){
            const uint32_t bd = sbase + 36864 + (wn + g*16 + lsel) * 144 + (kk + kof) * 2;
            ldm4(bh[g], bd);
            ldm4(bl[g], bd + 18432);
        }
        #pragma unroll
        for (int mt = 0; mt < 2; mt++)
            #pragma unroll
            for (int nt = 0; nt < 8; nt++){
                const int g = nt >> 1, s = nt & 1;
                mma_bf16(acc[mt][nt], ah[mt], bh[g][s], bh[g][s+2]);
                mma_bf16(acc[mt][nt], ah[mt], bl[g][s], bl[g][s+2]);
                mma_bf16(acc[mt][nt], al[mt], bh[g][s], bh[g][s+2]);
            }
    }

    __syncthreads();
    float* stg = (float*)smem;
    const int fr = lane >> 2, fc = (lane & 3) * 2;
    #pragma unroll
    for (int mt = 0; mt < 2; mt++)
        #pragma unroll
        for (int nt = 0; nt < 8; nt++){
            const int col = wn + nt*8 + fc;
            const int row0 = wm + mt*16 + fr;
            stg[row0*132 + col]       = acc[mt][nt][0];
            stg[row0*132 + col + 1]   = acc[mt][nt][1];
            stg[(row0+8)*132 + col]   = acc[mt][nt][2];
            stg[(row0+8)*132 + col+1] = acc[mt][nt][3];
        }
    __syncthreads();
    const int rr = tid >> 1, hf = tid & 1;
    const float* src = stg + rr * 132 + hf * 64;
    float* orow = Ob + (size_t)(i0 + rr) * TT + j0 + hf * 64;
    #pragma unroll
    for (int s = 0; s < 16; s++)
        *(float4*)(orow + s*4) = *(const float4*)(src + s*4);
}

// ---------------- kernel 3: rel-shift + softmax -> normalized bf16 probs ----------------
__global__ __launch_bounds__(256) void softmax_shift_kernel(int bh0)
{
    const int i  = blockIdx.x;
    const int bh = bh0 + blockIdx.y;
    const int t  = threadIdx.x;
    const size_t rowoff = ((size_t)bh*SEQ + i) * TT;
    const float* ac = g_ac + rowoff;
    const float* bd0 = g_bd + rowoff;
    const float* bd1 = bd0 + TT;

    float sv[8];
    float lmax = -INFINITY;
    #pragma unroll
    for (int q = 0; q < 8; q++){
        const int j = q*256 + t;
        const int delta = j - i;
        float bd;
        if (delta <= 1024)      bd = bd0[delta + 1023];
        else if (delta == 1025) bd = 0.f;
        else                    bd = bd1[delta - 1026];
        const float s = (ac[j] + bd) * 0.125f;
        sv[q] = s;
        lmax = fmaxf(lmax, s);
    }
    __shared__ float sh[8];
    float wmax = warpReduceMax(lmax);
    if ((t & 31) == 0) sh[t >> 5] = wmax;
    __syncthreads();
    float mx = sh[0];
    #pragma unroll
    for (int w = 1; w < 8; w++) mx = fmaxf(mx, sh[w]);
    __syncthreads();

    float lsum = 0.f;
    #pragma unroll
    for (int q = 0; q < 8; q++){
        const float p = __expf(sv[q] - mx);
        sv[q] = p;
        lsum += p;
    }
    float wsum = warpReduceSum(lsum);
    if ((t & 31) == 0) sh[t >> 5] = wsum;
    __syncthreads();
    float sum = 0.f;
    #pragma unroll
    for (int w = 0; w < 8; w++) sum += sh[w];
    const float sinv = 1.f / sum;

    __nv_bfloat16* ph = g_ph + rowoff;
    #pragma unroll
    for (int q = 0; q < 8; q++){
        const int j = q*256 + t;
        ph[j] = __float2bfloat16(sv[q] * sinv);
    }
}

// ---------------- kernel 4: PV GEMM (P hi-only x V hi/lo) ----------------
#define PV_BUF   19456
#define PV_SMEM  (2*PV_BUF)

__global__ __launch_bounds__(256) void pv_mma_kernel(int bh0)
{
    extern __shared__ __align__(128) char smem[];
    const uint32_t sbase = smem_u32(smem);
    const int tid = threadIdx.x, lane = tid & 31, wid = tid >> 5;
    const int bh = bh0 + blockIdx.y;
    const int i0 = blockIdx.x * 128;
    const __nv_bfloat16* Php = g_ph + (size_t)bh*SEQ*TT + (size_t)i0*TT;
    const __nv_bfloat16* Vhp = g_vh + (size_t)bh*TT*DH;
    const __nv_bfloat16* Vlp = g_vl + (size_t)bh*TT*DH;

    const int wm = (wid & 3) * 32;
    const int wn = (wid >> 2) * 32;
    const int lsel = lane & 15;
    const int kof  = (lane < 16) ? 0 : 8;
    const int tcol = (lane >> 4) * 8;

    float acc[2][4][4];
    #pragma unroll
    for (int mt = 0; mt < 2; mt++)
        #pragma unroll
        for (int nt = 0; nt < 4; nt++)
            #pragma unroll
            for (int q = 0; q < 4; q++) acc[mt][nt][q] = 0.f;

    auto issue = [&](int c, int b){
        const int k0 = c * 32;
        const uint32_t sb = sbase + b * PV_BUF;
        #pragma unroll
        for (int p = 0; p < 2; p++){
            const int u = p * 256 + tid;
            const int row = u >> 2, seg = u & 3;
            const size_t go = (size_t)row * TT + k0 + seg * 8;
            cp16(sb + row * 80 + seg * 16, Php + go);
        }
        {
            const int row = tid >> 3, seg = tid & 7;
            const size_t go = (size_t)(k0 + row) * DH + seg * 8;
            const uint32_t so = row * 144 + seg * 16;
            cp16(sb + 10240 + so, Vhp + go);
            cp16(sb + 14848 + so, Vlp + go);
        }
        CP_COMMIT();
    };

    issue(0, 0);
    for (int c = 0; c < 64; c++){
        CP_WAIT0();
        __syncthreads();
        if (c + 1 < 64) issue(c + 1, (c + 1) & 1);
        const uint32_t sb = sbase + (c & 1) * PV_BUF;
        #pragma unroll
        for (int kk = 0; kk < 32; kk += 16){
            uint32_t ph[2][4], vh[2][4], vl[2][4];
            #pragma unroll
            for (int mt = 0; mt < 2; mt++){
                const uint32_t ad = sb + (wm + mt*16 + lsel) * 80 + (kk + kof) * 2;
                ldm4(ph[mt], ad);
            }
            #pragma unroll
            for (int g = 0; g < 2; g++){
                const uint32_t bd = sb + 10240 + (kk + lsel) * 144 + (wn + g*16 + tcol) * 2;
                ldm4t(vh[g], bd);
                ldm4t(vl[g], bd + 4608);
            }
            #pragma unroll
            for (int mt = 0; mt < 2; mt++)
                #pragma unroll
                for (int nt = 0; nt < 4; nt++){
                    const int g = nt >> 1, s = nt & 1;
                    mma_bf16(acc[mt][nt], ph[mt], vh[g][2*s], vh[g][2*s+1]);
                    mma_bf16(acc[mt][nt], ph[mt], vl[g][2*s], vl[g][2*s+1]);
                }
        }
    }

    __syncthreads();
    float* stg = (float*)smem;
    const int fr = lane >> 2, fc = (lane & 3) * 2;
    #pragma unroll
    for (int mt = 0; mt < 2; mt++)
        #pragma unroll
        for (int nt = 0; nt < 4; nt++){
            const int col = wn + nt*8 + fc;
            const int row0 = wm + mt*16 + fr;
            stg[row0*68 + col]       = acc[mt][nt][0];
            stg[row0*68 + col + 1]   = acc[mt][nt][1];
            stg[(row0+8)*68 + col]   = acc[mt][nt][2];
            stg[(row0+8)*68 + col+1] = acc[mt][nt][3];
        }
    __syncthreads();
    const int rr = tid >> 1, hf = tid & 1;
    const int b = bh >> 4, h = bh & 15;
    const int i = i0 + rr;
    const float* src = stg + rr * 68 + hf * 32;
    const size_t off = ((size_t)i*BATCH + b)*DM + h*DH + hf*32;
    #pragma unroll
    for (int s = 0; s < 4; s++){
        uint4 hi, lo;
        split8(src + s*8, hi, lo);
        *(uint4*)(g_avh + off + s*8) = hi;
        *(uint4*)(g_avl + off + s*8) = lo;
    }
}

// ---------------- kernel 5: bf16-split out projection + residual ----------------
__global__ __launch_bounds__(256) void outproj_mma_kernel(const float* __restrict__ x,
                                                          float* __restrict__ out)
{
    extern __shared__ __align__(128) char smem[];
    const uint32_t sbase = smem_u32(smem);
    const int tid = threadIdx.x, lane = tid & 31, wid = tid >> 5;
    const int n0 = blockIdx.x * 128;
    const int m0 = blockIdx.y * 128;
    const __nv_bfloat16* Ahp = g_avh + (size_t)m0 * 1024;
    const __nv_bfloat16* Alp = g_avl + (size_t)m0 * 1024;
    const __nv_bfloat16* Bhp = g_wohi + (size_t)n0 * 1024;
    const __nv_bfloat16* Blp = g_wolo + (size_t)n0 * 1024;

    const int wm = (wid & 3) * 32;
    const int wn = (wid >> 2) * 64;
    const int lsel = lane & 15;
    const int kof  = (lane < 16) ? 0 : 8;

    float acc[2][8][4];
    #pragma unroll
    for (int mt = 0; mt < 2; mt++)
        #pragma unroll
        for (int nt = 0; nt < 8; nt++)
            #pragma unroll
            for (int q = 0; q < 4; q++) acc[mt][nt][q] = 0.f;

    auto issue = [&](int c, int b){
        const int k0 = c * 32;
        const uint32_t sb = sbase + b * PJ_BUF;
        #pragma unroll
        for (int p = 0; p < 2; p++){
            const int u = p * 256 + tid;
            const int row = u >> 2, seg = u & 3;
            const size_t go = (size_t)row * 1024 + k0 + seg * 8;
            const uint32_t so = row * 80 + seg * 16;
            cp16(sb + so,          Ahp + go);
            cp16(sb + 10240 + so,  Alp + go);
            cp16(sb + 20480 + so,  Bhp + go);
            cp16(sb + 30720 + so,  Blp + go);
        }
        CP_COMMIT();
    };

    issue(0, 0);
    for (int c = 0; c < 32; c++){
        CP_WAIT0();
        __syncthreads();
        if (c + 1 < 32) issue(c + 1, (c + 1) & 1);
        const uint32_t sb = sbase + (c & 1) * PJ_BUF;
        #pragma unroll
        for (int kk = 0; kk < 32; kk += 16){
            uint32_t ah[2][4], al[2][4], bh[4][4], bl[4][4];
            #pragma unroll
            for (int mt = 0; mt < 2; mt++){
                const uint32_t ad = sb + (wm + mt*16 + lsel) * 80 + (kk + kof) * 2;
                ldm4(ah[mt], ad);
                ldm4(al[mt], ad + 10240);
            }
            #pragma unroll
            for (int g = 0; g < 4; g++){
                const uint32_t bd = sb + 20480 + (wn + g*16 + lsel) * 80 + (kk + kof) * 2;
                ldm4(bh[g], bd);
                ldm4(bl[g], bd + 10240);
            }
            #pragma unroll
            for (int mt = 0; mt < 2; mt++)
                #pragma unroll
                for (int nt = 0; nt < 8; nt++){
                    const int g = nt >> 1, s = nt & 1;
                    mma_bf16(acc[mt][nt], ah[mt], bh[g][s], bh[g][s+2]);
                    mma_bf16(acc[mt][nt], ah[mt], bl[g][s], bl[g][s+2]);
                    mma_bf16(acc[mt][nt], al[mt], bh[g][s], bh[g][s+2]);
                }
        }
    }

    __syncthreads();
    float* stg = (float*)smem;
    const int fr = lane >> 2, fc = (lane & 3) * 2;
    #pragma unroll
    for (int mt = 0; mt < 2; mt++)
        #pragma unroll
        for (int nt = 0; nt < 8; nt++){
            const int col = wn + nt*8 + fc;
            const int row0 = wm + mt*16 + fr;
            stg[row0*132 + col]       = acc[mt][nt][0];
            stg[row0*132 + col + 1]   = acc[mt][nt][1];
            stg[(row0+8)*132 + col]   = acc[mt][nt][2];
            stg[(row0+8)*132 + col+1] = acc[mt][nt][3];
        }
    __syncthreads();
    const int rr = tid >> 1, hf = tid & 1;
    const int m = m0 + rr;
    const float* src = stg + rr * 132 + hf * 64;
    const float* xr = x + (size_t)m*DM + n0 + hf*64;
    float* orow = out + (size_t)m*DM + n0 + hf*64;
    #pragma unroll
    for (int s = 0; s < 16; s++){
        float4 v = *(const float4*)(src + s*4);
        float4 xx = *(const float4*)(xr + s*4);
        *(float4*)(orow + s*4) = make_float4(v.x+xx.x, v.y+xx.y, v.z+xx.z, v.w+xx.w);
    }
}

// ---------------- kernel 6: LayerNorm ----------------
__global__ __launch_bounds__(256) void ln_kernel(float* __restrict__ out,
                                                 const float* __restrict__ gamma,
                                                 const float* __restrict__ beta)
{
    const int row = blockIdx.x;
    float* y = out + (size_t)row * DM;
    const int t = threadIdx.x;
    float v[4];
    float s = 0.f, sq = 0.f;
    #pragma unroll
    for (int q = 0; q < 4; q++){
        v[q] = y[q*256 + t];
        s += v[q];
        sq += v[q]*v[q];
    }
    __shared__ float sh[16];
    float ws = warpReduceSum(s);
    float wq = warpReduceSum(sq);
    if ((t & 31) == 0){ sh[t>>5] = ws; sh[8 + (t>>5)] = wq; }
    __syncthreads();
    s = 0.f; sq = 0.f;
    #pragma unroll
    for (int w = 0; w < 8; w++){ s += sh[w]; sq += sh[8+w]; }
    const float mu = s * (1.f/1024.f);
    const float var = sq * (1.f/1024.f) - mu*mu;
    const float rstd = rsqrtf(var + 1e-5f);
    #pragma unroll
    for (int q = 0; q < 4; q++){
        const int d = q*256 + t;
        y[d] = gamma[d] * ((v[q] - mu) * rstd) + beta[d];
    }
}

// ---------------- launch ----------------
#define NCHUNK 4
#define CHBH   16

extern "C" void kernel_launch(void* const* d_in, const int* in_sizes, int n_in,
                              void* d_out, int out_size)
{
    const float* x     = (const float*)d_in[0];
    const float* mem   = (const float*)d_in[1];
    const float* pos   = (const float*)d_in[2];
    const float* pbu   = (const float*)d_in[3];
    const float* pbv   = (const float*)d_in[4];
    const float* Wqkv  = (const float*)d_in[5];
    const float* Wrel  = (const float*)d_in[6];
    const float* Wo    = (const float*)d_in[7];
    const float* gamma = (const float*)d_in[8];
    const float* beta  = (const float*)d_in[9];
    float* out = (float*)d_out;

    static cudaStream_t s1 = nullptr;
    static cudaEvent_t evS[NCHUNK], evM[NCHUNK];
    if (!s1){
        cudaStreamCreateWithFlags(&s1, cudaStreamNonBlocking);
        for (int c = 0; c < NCHUNK; c++){
            cudaEventCreateWithFlags(&evS[c], cudaEventDisableTiming);
            cudaEventCreateWithFlags(&evM[c], cudaEventDisableTiming);
        }
        cudaFuncSetAttribute(proj_mma_kernel,    cudaFuncAttributeMaxDynamicSharedMemorySize, PJ_SMEM);
        cudaFuncSetAttribute(score_mma_kernel,   cudaFuncAttributeMaxDynamicSharedMemorySize, SC_SMEM);
        cudaFuncSetAttribute(pv_mma_kernel,      cudaFuncAttributeMaxDynamicSharedMemorySize, PV_SMEM);
        cudaFuncSetAttribute(outproj_mma_kernel, cudaFuncAttributeMaxDynamicSharedMemorySize, PJ_SMEM);
    }

    conv_kernel<<<21504, 256>>>(x, mem, pos, Wqkv, Wrel, Wo);
    proj_mma_kernel<<<1792, 256, PJ_SMEM>>>(pbu, pbv);

    // score chunks on stream 0; softmax chunks overlap on s1
    for (int c = 0; c < NCHUNK; c++){
        score_mma_kernel<<<dim3(16, 8, 2*CHBH), 256, SC_SMEM>>>(c * CHBH);
        cudaEventRecord(evS[c], 0);
        cudaStreamWaitEvent(s1, evS[c], 0);
        softmax_shift_kernel<<<dim3(1024, CHBH), 256, 0, s1>>>(c * CHBH);
        cudaEventRecord(evM[c], s1);
    }
    // pvA: bh 0..47 (384 CTAs) — waits only chunks 0-2; overlaps with softmax chunk 3
    cudaStreamWaitEvent(0, evM[0], 0);
    cudaStreamWaitEvent(0, evM[1], 0);
    cudaStreamWaitEvent(0, evM[2], 0);
    pv_mma_kernel<<<dim3(8, 48), 256, PV_SMEM>>>(0);
    // pvB: bh 48..63 (128 CTAs) — waits chunk 3
    cudaStreamWaitEvent(0, evM[3], 0);
    pv_mma_kernel<<<dim3(8, 16), 256, PV_SMEM>>>(48);

    outproj_mma_kernel<<<dim3(8, 32), 256, PJ_SMEM>>>(x, out);
    ln_kernel<<<4096, 256>>>(out, gamma, beta);
}

// round 8
// speedup vs baseline: 1.8688x; 1.7649x over previous
#include <cuda_runtime.h>
#include <cuda_fp16.h>
#include <math.h>
#include <stdint.h>

#define SEQ   1024
#define MEMN  1024
#define TT    2048
#define BATCH 4
#define NH    16
#define DH    64
#define DM    1024
#define BH    (BATCH*NH)   // 64

// ---------------- scratch (device globals, all fp16 single precision) ----------------
__device__ __half g_ac[(size_t)BH*SEQ*TT];     // AC scores fp16
__device__ __half g_bd[(size_t)BH*SEQ*TT];     // BD raw fp16

__device__ __half g_c [(size_t)8192*1024];     // concat(mem, x)
__device__ __half g_p [(size_t)8192*1024];     // pos_emb
__device__ __half g_w [(size_t)4096*1024];     // concat(Wqkv, Wrel)
__device__ __half g_wo[(size_t)1024*1024];     // Wo

__device__ __half g_qu[(size_t)BH*SEQ*DH];
__device__ __half g_qv[(size_t)BH*SEQ*DH];
__device__ __half g_k [(size_t)BH*TT*DH];
__device__ __half g_v [(size_t)BH*TT*DH];
__device__ __half g_r [(size_t)BH*TT*DH];

__device__ __half g_ph[(size_t)BH*SEQ*TT];     // normalized probs fp16
__device__ __half g_av[(size_t)SEQ*BATCH*DM];  // attn_vec fp16

// ---------------- helpers ----------------
__device__ __forceinline__ uint32_t smem_u32(const void* p){
    uint32_t a;
    asm("{ .reg .u64 t; cvta.to.shared.u64 t, %1; cvt.u32.u64 %0, t; }" : "=r"(a) : "l"(p));
    return a;
}
__device__ __forceinline__ void cp16(uint32_t s, const void* g){
    asm volatile("cp.async.cg.shared.global [%0], [%1], 16;" :: "r"(s), "l"(g));
}
#define CP_COMMIT() asm volatile("cp.async.commit_group;" ::: "memory")
#define CP_WAIT0()  asm volatile("cp.async.wait_group 0;" ::: "memory")

__device__ __forceinline__ void ldm4(uint32_t* r, uint32_t addr){
    asm volatile("ldmatrix.sync.aligned.m8n8.x4.shared.b16 {%0,%1,%2,%3}, [%4];"
        : "=r"(r[0]), "=r"(r[1]), "=r"(r[2]), "=r"(r[3]) : "r"(addr));
}
__device__ __forceinline__ void ldm4t(uint32_t* r, uint32_t addr){
    asm volatile("ldmatrix.sync.aligned.m8n8.x4.trans.shared.b16 {%0,%1,%2,%3}, [%4];"
        : "=r"(r[0]), "=r"(r[1]), "=r"(r[2]), "=r"(r[3]) : "r"(addr));
}
__device__ __forceinline__ void mma_f16(float* c, const uint32_t* a, uint32_t b0, uint32_t b1){
    asm volatile("mma.sync.aligned.m16n8k16.row.col.f32.f16.f16.f32 "
        "{%0,%1,%2,%3}, {%4,%5,%6,%7}, {%8,%9}, {%0,%1,%2,%3};"
        : "+f"(c[0]), "+f"(c[1]), "+f"(c[2]), "+f"(c[3])
        : "r"(a[0]), "r"(a[1]), "r"(a[2]), "r"(a[3]), "r"(b0), "r"(b1));
}
__device__ __forceinline__ uint4 pack8h(const float* v){
    __half2 a = __floats2half2_rn(v[0], v[1]);
    __half2 b = __floats2half2_rn(v[2], v[3]);
    __half2 c = __floats2half2_rn(v[4], v[5]);
    __half2 d = __floats2half2_rn(v[6], v[7]);
    uint4 r;
    r.x = *(uint32_t*)&a; r.y = *(uint32_t*)&b;
    r.z = *(uint32_t*)&c; r.w = *(uint32_t*)&d;
    return r;
}

__device__ __forceinline__ float warpReduceSum(float v){
    #pragma unroll
    for (int o = 16; o > 0; o >>= 1) v += __shfl_xor_sync(0xffffffffu, v, o);
    return v;
}
__device__ __forceinline__ float warpReduceMax(float v){
    #pragma unroll
    for (int o = 16; o > 0; o >>= 1) v = fmaxf(v, __shfl_xor_sync(0xffffffffu, v, o));
    return v;
}

// ---------------- kernel 0: fp32 -> fp16 conversion ----------------
__global__ __launch_bounds__(256) void conv_kernel(
    const float* __restrict__ x, const float* __restrict__ mem,
    const float* __restrict__ pos, const float* __restrict__ Wqkv,
    const float* __restrict__ Wrel, const float* __restrict__ Wo)
{
    const size_t u = (size_t)blockIdx.x * 256 + threadIdx.x;
    const float* src;
    __half* dst;
    size_t elem;
    if (u < 2097152) {
        elem = u * 4;
        const size_t row = elem >> 10, col = elem & 1023;
        src = (row < 4096) ? (mem + row*1024 + col) : (x + (row-4096)*1024 + col);
        dst = g_c + elem;
    } else if (u < 4194304) {
        elem = (u - 2097152) * 4;
        src = pos + elem;
        dst = g_p + elem;
    } else if (u < 5242880) {
        elem = (u - 4194304) * 4;
        const size_t row = elem >> 10, col = elem & 1023;
        src = (row < 3072) ? (Wqkv + row*1024 + col) : (Wrel + (row-3072)*1024 + col);
        dst = g_w + elem;
    } else {
        elem = (u - 5242880) * 4;
        src = Wo + elem;
        dst = g_wo + elem;
    }
    float4 v = *(const float4*)src;
    __half2 h01 = __floats2half2_rn(v.x, v.y);
    __half2 h23 = __floats2half2_rn(v.z, v.w);
    *(uint2*)dst = make_uint2(*(uint32_t*)&h01, *(uint32_t*)&h23);
}

// ---------------- kernel 1: fp16 projection GEMM ----------------
// 1792 blocks: q-category tiles only cover m>=4096 (x rows).
#define PJ_BUF   20480
#define PJ_SMEM  67584   // >= 2*PJ_BUF and >= 128*132*4 fp32 staging

__global__ __launch_bounds__(256) void proj_mma_kernel(
    const float* __restrict__ pbu, const float* __restrict__ pbv)
{
    extern __shared__ __align__(128) char smem[];
    const uint32_t sbase = smem_u32(smem);
    const int tid = threadIdx.x, lane = tid & 31, wid = tid >> 5;
    const int bid = blockIdx.x;
    int n0, m0;
    if (bid < 256){ n0 = (bid & 7) * 128; m0 = 4096 + (bid >> 3) * 128; }
    else { const int b2 = bid - 256; n0 = 1024 + (b2 % 24) * 128; m0 = (b2 / 24) * 128; }

    const bool is_rel = (n0 >= 3072);
    const __half* Ap = (is_rel ? g_p : g_c) + (size_t)m0 * 1024;
    const __half* Bp = g_w + (size_t)n0 * 1024;

    const int wm = (wid & 3) * 32;
    const int wn = (wid >> 2) * 64;
    const int lsel = lane & 15;
    const int kof  = (lane < 16) ? 0 : 8;

    float acc[2][8][4];
    #pragma unroll
    for (int mt = 0; mt < 2; mt++)
        #pragma unroll
        for (int nt = 0; nt < 8; nt++)
            #pragma unroll
            for (int q = 0; q < 4; q++) acc[mt][nt][q] = 0.f;

    auto issue = [&](int c, int b){
        const int k0 = c * 32;
        const uint32_t sb = sbase + b * PJ_BUF;
        #pragma unroll
        for (int p = 0; p < 2; p++){
            const int u = p * 256 + tid;
            const int row = u >> 2, seg = u & 3;
            const size_t go = (size_t)row * 1024 + k0 + seg * 8;
            const uint32_t so = row * 80 + seg * 16;
            cp16(sb + so,         Ap + go);
            cp16(sb + 10240 + so, Bp + go);
        }
        CP_COMMIT();
    };

    issue(0, 0);
    for (int c = 0; c < 32; c++){
        CP_WAIT0();
        __syncthreads();
        if (c + 1 < 32) issue(c + 1, (c + 1) & 1);
        const uint32_t sb = sbase + (c & 1) * PJ_BUF;
        #pragma unroll
        for (int kk = 0; kk < 32; kk += 16){
            uint32_t ah[2][4], bh[4][4];
            #pragma unroll
            for (int mt = 0; mt < 2; mt++)
                ldm4(ah[mt], sb + (wm + mt*16 + lsel) * 80 + (kk + kof) * 2);
            #pragma unroll
            for (int g = 0; g < 4; g++)
                ldm4(bh[g], sb + 10240 + (wn + g*16 + lsel) * 80 + (kk + kof) * 2);
            #pragma unroll
            for (int mt = 0; mt < 2; mt++)
                #pragma unroll
                for (int nt = 0; nt < 8; nt++){
                    const int g = nt >> 1, s = nt & 1;
                    mma_f16(acc[mt][nt], ah[mt], bh[g][s], bh[g][s+2]);
                }
        }
    }

    __syncthreads();
    float* stg = (float*)smem;
    const int fr = lane >> 2, fc = (lane & 3) * 2;
    #pragma unroll
    for (int mt = 0; mt < 2; mt++)
        #pragma unroll
        for (int nt = 0; nt < 8; nt++){
            const int col = wn + nt*8 + fc;
            const int row0 = wm + mt*16 + fr;
            stg[row0*132 + col]       = acc[mt][nt][0];
            stg[row0*132 + col + 1]   = acc[mt][nt][1];
            stg[(row0+8)*132 + col]   = acc[mt][nt][2];
            stg[(row0+8)*132 + col+1] = acc[mt][nt][3];
        }
    __syncthreads();

    const int rr = tid >> 1, hf = tid & 1;
    const int m = m0 + rr;
    const int t_ = m >> 2, b_ = m & 3;
    const float* src = stg + rr * 132 + hf * 64;
    const int nbase = n0 + hf * 64;
    const int cat = n0 >> 10;
    if (cat == 0){
        const int i = t_ - MEMN;
        const int h = nbase >> 6;
        const size_t off = (((size_t)(b_*NH + h))*SEQ + i)*DH;
        #pragma unroll
        for (int s = 0; s < 8; s++){
            float qu8[8], qv8[8];
            #pragma unroll
            for (int e = 0; e < 8; e++){
                const float v = src[s*8 + e];
                qu8[e] = v + pbu[nbase + s*8 + e];
                qv8[e] = v + pbv[nbase + s*8 + e];
            }
            *(uint4*)(g_qu + off + s*8) = pack8h(qu8);
            *(uint4*)(g_qv + off + s*8) = pack8h(qv8);
        }
    } else {
        const int nn = nbase - cat*1024;
        const int h = nn >> 6;
        __half* bptr = (cat == 1) ? g_k : (cat == 2) ? g_v : g_r;
        const size_t off = (((size_t)(b_*NH + h))*TT + t_)*DH;
        #pragma unroll
        for (int s = 0; s < 8; s++)
            *(uint4*)(bptr + off + s*8) = pack8h(src + s*8);
    }
}

// ---------------- kernel 2: fp16 score GEMMs (K=64), chunked over bh ----------------
#define SC_SMEM 67584   // >= 36864 operands, >= fp32 staging

__global__ __launch_bounds__(256) void score_mma_kernel(int bh0)
{
    extern __shared__ __align__(128) char smem[];
    const uint32_t sbase = smem_u32(smem);
    const int tid = threadIdx.x, lane = tid & 31, wid = tid >> 5;
    const int z = blockIdx.z;
    const int bh = bh0 + (z >> 1), which = z & 1;
    const __half* Ap = (which ? g_qv : g_qu) + (size_t)bh * SEQ * DH;
    const __half* Bp = (which ? g_r  : g_k ) + (size_t)bh * TT  * DH;
    __half* Ob = (which ? g_bd : g_ac) + (size_t)bh * SEQ * TT;
    const int i0 = blockIdx.y * 128;
    const int j0 = blockIdx.x * 128;

    const int wm = (wid & 3) * 32;
    const int wn = (wid >> 2) * 64;
    const int lsel = lane & 15;
    const int kof  = (lane < 16) ? 0 : 8;

    // A @0 (128 rows x 64 fp16, stride 144B), B @18432
    #pragma unroll
    for (int p = 0; p < 4; p++){
        const int u = p * 256 + tid;
        const int row = u >> 3, seg = u & 7;
        const uint32_t so = row * 144 + seg * 16;
        cp16(sbase + so,         Ap + (size_t)(i0 + row) * DH + seg * 8);
        cp16(sbase + 18432 + so, Bp + (size_t)(j0 + row) * DH + seg * 8);
    }
    CP_COMMIT();

    float acc[2][8][4];
    #pragma unroll
    for (int mt = 0; mt < 2; mt++)
        #pragma unroll
        for (int nt = 0; nt < 8; nt++)
            #pragma unroll
            for (int q = 0; q < 4; q++) acc[mt][nt][q] = 0.f;

    CP_WAIT0();
    __syncthreads();

    #pragma unroll
    for (int kk = 0; kk < 64; kk += 16){
        uint32_t ah[2][4], bh[4][4];
        #pragma unroll
        for (int mt = 0; mt < 2; mt++)
            ldm4(ah[mt], sbase + (wm + mt*16 + lsel) * 144 + (kk + kof) * 2);
        #pragma unroll
        for (int g = 0; g < 4; g++)
            ldm4(bh[g], sbase + 18432 + (wn + g*16 + lsel) * 144 + (kk + kof) * 2);
        #pragma unroll
        for (int mt = 0; mt < 2; mt++)
            #pragma unroll
            for (int nt = 0; nt < 8; nt++){
                const int g = nt >> 1, s = nt & 1;
                mma_f16(acc[mt][nt], ah[mt], bh[g][s], bh[g][s+2]);
            }
    }

    __syncthreads();
    float* stg = (float*)smem;
    const int fr = lane >> 2, fc = (lane & 3) * 2;
    #pragma unroll
    for (int mt = 0; mt < 2; mt++)
        #pragma unroll
        for (int nt = 0; nt < 8; nt++){
            const int col = wn + nt*8 + fc;
            const int row0 = wm + mt*16 + fr;
            stg[row0*132 + col]       = acc[mt][nt][0];
            stg[row0*132 + col + 1]   = acc[mt][nt][1];
            stg[(row0+8)*132 + col]   = acc[mt][nt][2];
            stg[(row0+8)*132 + col+1] = acc[mt][nt][3];
        }
    __syncthreads();
    const int rr = tid >> 1, hf = tid & 1;
    const float* src = stg + rr * 132 + hf * 64;
    __half* orow = Ob + (size_t)(i0 + rr) * TT + j0 + hf * 64;
    #pragma unroll
    for (int s = 0; s < 8; s++)
        *(uint4*)(orow + s*8) = pack8h(src + s*8);
}

// ---------------- kernel 3: rel-shift + softmax -> fp16 probs ----------------
__global__ __launch_bounds__(256) void softmax_shift_kernel(int bh0)
{
    const int i  = blockIdx.x;
    const int bh = bh0 + blockIdx.y;
    const int t  = threadIdx.x;
    const size_t rowoff = ((size_t)bh*SEQ + i) * TT;
    const __half* ac = g_ac + rowoff;
    const __half* bd0 = g_bd + rowoff;
    const __half* bd1 = bd0 + TT;

    float sv[8];
    float lmax = -INFINITY;
    #pragma unroll
    for (int q = 0; q < 8; q++){
        const int j = q*256 + t;
        const int delta = j - i;
        float bd;
        if (delta <= 1024)      bd = __half2float(bd0[delta + 1023]);
        else if (delta == 1025) bd = 0.f;
        else                    bd = __half2float(bd1[delta - 1026]);
        const float s = (__half2float(ac[j]) + bd) * 0.125f;
        sv[q] = s;
        lmax = fmaxf(lmax, s);
    }
    __shared__ float sh[8];
    float wmax = warpReduceMax(lmax);
    if ((t & 31) == 0) sh[t >> 5] = wmax;
    __syncthreads();
    float mx = sh[0];
    #pragma unroll
    for (int w = 1; w < 8; w++) mx = fmaxf(mx, sh[w]);
    __syncthreads();

    float lsum = 0.f;
    #pragma unroll
    for (int q = 0; q < 8; q++){
        const float p = __expf(sv[q] - mx);
        sv[q] = p;
        lsum += p;
    }
    float wsum = warpReduceSum(lsum);
    if ((t & 31) == 0) sh[t >> 5] = wsum;
    __syncthreads();
    float sum = 0.f;
    #pragma unroll
    for (int w = 0; w < 8; w++) sum += sh[w];
    const float sinv = 1.f / sum;

    __half* ph = g_ph + rowoff;
    #pragma unroll
    for (int q = 0; q < 8; q++){
        const int j = q*256 + t;
        ph[j] = __float2half_rn(sv[q] * sinv);
    }
}

// ---------------- kernel 4: fp16 PV GEMM ----------------
#define PV_BUF   14848
#define PV_SMEM  34816   // >= 2*PV_BUF, >= 128*68*4 fp32 staging

__global__ __launch_bounds__(256) void pv_mma_kernel(int bh0)
{
    extern __shared__ __align__(128) char smem[];
    const uint32_t sbase = smem_u32(smem);
    const int tid = threadIdx.x, lane = tid & 31, wid = tid >> 5;
    const int bh = bh0 + blockIdx.y;
    const int i0 = blockIdx.x * 128;
    const __half* Pp = g_ph + (size_t)bh*SEQ*TT + (size_t)i0*TT;
    const __half* Vp = g_v + (size_t)bh*TT*DH;

    const int wm = (wid & 3) * 32;
    const int wn = (wid >> 2) * 32;
    const int lsel = lane & 15;
    const int kof  = (lane < 16) ? 0 : 8;
    const int tcol = (lane >> 4) * 8;

    float acc[2][4][4];
    #pragma unroll
    for (int mt = 0; mt < 2; mt++)
        #pragma unroll
        for (int nt = 0; nt < 4; nt++)
            #pragma unroll
            for (int q = 0; q < 4; q++) acc[mt][nt][q] = 0.f;

    auto issue = [&](int c, int b){
        const int k0 = c * 32;
        const uint32_t sb = sbase + b * PV_BUF;
        #pragma unroll
        for (int p = 0; p < 2; p++){
            const int u = p * 256 + tid;
            const int row = u >> 2, seg = u & 3;
            cp16(sb + row * 80 + seg * 16, Pp + (size_t)row * TT + k0 + seg * 8);
        }
        {
            const int row = tid >> 3, seg = tid & 7;
            cp16(sb + 10240 + row * 144 + seg * 16, Vp + (size_t)(k0 + row) * DH + seg * 8);
        }
        CP_COMMIT();
    };

    issue(0, 0);
    for (int c = 0; c < 64; c++){
        CP_WAIT0();
        __syncthreads();
        if (c + 1 < 64) issue(c + 1, (c + 1) & 1);
        const uint32_t sb = sbase + (c & 1) * PV_BUF;
        #pragma unroll
        for (int kk = 0; kk < 32; kk += 16){
            uint32_t ph[2][4], vh[2][4];
            #pragma unroll
            for (int mt = 0; mt < 2; mt++)
                ldm4(ph[mt], sb + (wm + mt*16 + lsel) * 80 + (kk + kof) * 2);
            #pragma unroll
            for (int g = 0; g < 2; g++)
                ldm4t(vh[g], sb + 10240 + (kk + lsel) * 144 + (wn + g*16 + tcol) * 2);
            #pragma unroll
            for (int mt = 0; mt < 2; mt++)
                #pragma unroll
                for (int nt = 0; nt < 4; nt++){
                    const int g = nt >> 1, s = nt & 1;
                    mma_f16(acc[mt][nt], ph[mt], vh[g][2*s], vh[g][2*s+1]);
                }
        }
    }

    __syncthreads();
    float* stg = (float*)smem;
    const int fr = lane >> 2, fc = (lane & 3) * 2;
    #pragma unroll
    for (int mt = 0; mt < 2; mt++)
        #pragma unroll
        for (int nt = 0; nt < 4; nt++){
            const int col = wn + nt*8 + fc;
            const int row0 = wm + mt*16 + fr;
            stg[row0*68 + col]       = acc[mt][nt][0];
            stg[row0*68 + col + 1]   = acc[mt][nt][1];
            stg[(row0+8)*68 + col]   = acc[mt][nt][2];
            stg[(row0+8)*68 + col+1] = acc[mt][nt][3];
        }
    __syncthreads();
    const int rr = tid >> 1, hf = tid & 1;
    const int b = bh >> 4, h = bh & 15;
    const int i = i0 + rr;
    const float* src = stg + rr * 68 + hf * 32;
    const size_t off = ((size_t)i*BATCH + b)*DM + h*DH + hf*32;
    #pragma unroll
    for (int s = 0; s < 4; s++)
        *(uint4*)(g_av + off + s*8) = pack8h(src + s*8);
}

// ---------------- kernel 5: fp16 out projection + residual ----------------
#define OP_BUF   20480
#define OP_SMEM  67584

__global__ __launch_bounds__(256) void outproj_mma_kernel(const float* __restrict__ x,
                                                          float* __restrict__ out)
{
    extern __shared__ __align__(128) char smem[];
    const uint32_t sbase = smem_u32(smem);
    const int tid = threadIdx.x, lane = tid & 31, wid = tid >> 5;
    const int n0 = blockIdx.x * 128;
    const int m0 = blockIdx.y * 128;
    const __half* Ap = g_av + (size_t)m0 * 1024;
    const __half* Bp = g_wo + (size_t)n0 * 1024;

    const int wm = (wid & 3) * 32;
    const int wn = (wid >> 2) * 64;
    const int lsel = lane & 15;
    const int kof  = (lane < 16) ? 0 : 8;

    float acc[2][8][4];
    #pragma unroll
    for (int mt = 0; mt < 2; mt++)
        #pragma unroll
        for (int nt = 0; nt < 8; nt++)
            #pragma unroll
            for (int q = 0; q < 4; q++) acc[mt][nt][q] = 0.f;

    auto issue = [&](int c, int b){
        const int k0 = c * 32;
        const uint32_t sb = sbase + b * OP_BUF;
        #pragma unroll
        for (int p = 0; p < 2; p++){
            const int u = p * 256 + tid;
            const int row = u >> 2, seg = u & 3;
            const size_t go = (size_t)row * 1024 + k0 + seg * 8;
            const uint32_t so = row * 80 + seg * 16;
            cp16(sb + so,         Ap + go);
            cp16(sb + 10240 + so, Bp + go);
        }
        CP_COMMIT();
    };

    issue(0, 0);
    for (int c = 0; c < 32; c++){
        CP_WAIT0();
        __syncthreads();
        if (c + 1 < 32) issue(c + 1, (c + 1) & 1);
        const uint32_t sb = sbase + (c & 1) * OP_BUF;
        #pragma unroll
        for (int kk = 0; kk < 32; kk += 16){
            uint32_t ah[2][4], bh[4][4];
            #pragma unroll
            for (int mt = 0; mt < 2; mt++)
                ldm4(ah[mt], sb + (wm + mt*16 + lsel) * 80 + (kk + kof) * 2);
            #pragma unroll
            for (int g = 0; g < 4; g++)
                ldm4(bh[g], sb + 10240 + (wn + g*16 + lsel) * 80 + (kk + kof) * 2);
            #pragma unroll
            for (int mt = 0; mt < 2; mt++)
                #pragma unroll
                for (int nt = 0; nt < 8; nt++){
                    const int g = nt >> 1, s = nt & 1;
                    mma_f16(acc[mt][nt], ah[mt], bh[g][s], bh[g][s+2]);
                }
        }
    }

    __syncthreads();
    float* stg = (float*)smem;
    const int fr = lane >> 2, fc = (lane & 3) * 2;
    #pragma unroll
    for (int mt = 0; mt < 2; mt++)
        #pragma unroll
        for (int nt = 0; nt < 8; nt++){
            const int col = wn + nt*8 + fc;
            const int row0 = wm + mt*16 + fr;
            stg[row0*132 + col]       = acc[mt][nt][0];
            stg[row0*132 + col + 1]   = acc[mt][nt][1];
            stg[(row0+8)*132 + col]   = acc[mt][nt][2];
            stg[(row0+8)*132 + col+1] = acc[mt][nt][3];
        }
    __syncthreads();
    const int rr = tid >> 1, hf = tid & 1;
    const int m = m0 + rr;
    const float* src = stg + rr * 132 + hf * 64;
    const float* xr = x + (size_t)m*DM + n0 + hf*64;
    float* orow = out + (size_t)m*DM + n0 + hf*64;
    #pragma unroll
    for (int s = 0; s < 16; s++){
        float4 v = *(const float4*)(src + s*4);
        float4 xx = *(const float4*)(xr + s*4);
        *(float4*)(orow + s*4) = make_float4(v.x+xx.x, v.y+xx.y, v.z+xx.z, v.w+xx.w);
    }
}

// ---------------- kernel 6: LayerNorm ----------------
__global__ __launch_bounds__(256) void ln_kernel(float* __restrict__ out,
                                                 const float* __restrict__ gamma,
                                                 const float* __restrict__ beta)
{
    const int row = blockIdx.x;
    float* y = out + (size_t)row * DM;
    const int t = threadIdx.x;
    float v[4];
    float s = 0.f, sq = 0.f;
    #pragma unroll
    for (int q = 0; q < 4; q++){
        v[q] = y[q*256 + t];
        s += v[q];
        sq += v[q]*v[q];
    }
    __shared__ float sh[16];
    float ws = warpReduceSum(s);
    float wq = warpReduceSum(sq);
    if ((t & 31) == 0){ sh[t>>5] = ws; sh[8 + (t>>5)] = wq; }
    __syncthreads();
    s = 0.f; sq = 0.f;
    #pragma unroll
    for (int w = 0; w < 8; w++){ s += sh[w]; sq += sh[8+w]; }
    const float mu = s * (1.f/1024.f);
    const float var = sq * (1.f/1024.f) - mu*mu;
    const float rstd = rsqrtf(var + 1e-5f);
    #pragma unroll
    for (int q = 0; q < 4; q++){
        const int d = q*256 + t;
        y[d] = gamma[d] * ((v[q] - mu) * rstd) + beta[d];
    }
}

// ---------------- launch ----------------
#define NCHUNK 4
#define CHBH   16

extern "C" void kernel_launch(void* const* d_in, const int* in_sizes, int n_in,
                              void* d_out, int out_size)
{
    const float* x     = (const float*)d_in[0];
    const float* mem   = (const float*)d_in[1];
    const float* pos   = (const float*)d_in[2];
    const float* pbu   = (const float*)d_in[3];
    const float* pbv   = (const float*)d_in[4];
    const float* Wqkv  = (const float*)d_in[5];
    const float* Wrel  = (const float*)d_in[6];
    const float* Wo    = (const float*)d_in[7];
    const float* gamma = (const float*)d_in[8];
    const float* beta  = (const float*)d_in[9];
    float* out = (float*)d_out;

    static cudaStream_t s1 = nullptr;
    static cudaEvent_t evS[NCHUNK], evM[NCHUNK];
    if (!s1){
        cudaStreamCreateWithFlags(&s1, cudaStreamNonBlocking);
        for (int c = 0; c < NCHUNK; c++){
            cudaEventCreateWithFlags(&evS[c], cudaEventDisableTiming);
            cudaEventCreateWithFlags(&evM[c], cudaEventDisableTiming);
        }
        cudaFuncSetAttribute(proj_mma_kernel,    cudaFuncAttributeMaxDynamicSharedMemorySize, PJ_SMEM);
        cudaFuncSetAttribute(score_mma_kernel,   cudaFuncAttributeMaxDynamicSharedMemorySize, SC_SMEM);
        cudaFuncSetAttribute(pv_mma_kernel,      cudaFuncAttributeMaxDynamicSharedMemorySize, PV_SMEM);
        cudaFuncSetAttribute(outproj_mma_kernel, cudaFuncAttributeMaxDynamicSharedMemorySize, OP_SMEM);
    }

    conv_kernel<<<21504, 256>>>(x, mem, pos, Wqkv, Wrel, Wo);
    proj_mma_kernel<<<1792, 256, PJ_SMEM>>>(pbu, pbv);

    // score chunks on stream 0; softmax chunks overlap on s1
    for (int c = 0; c < NCHUNK; c++){
        score_mma_kernel<<<dim3(16, 8, 2*CHBH), 256, SC_SMEM>>>(c * CHBH);
        cudaEventRecord(evS[c], 0);
        cudaStreamWaitEvent(s1, evS[c], 0);
        softmax_shift_kernel<<<dim3(1024, CHBH), 256, 0, s1>>>(c * CHBH);
        cudaEventRecord(evM[c], s1);
    }
    // pvA: bh 0..47 (384 CTAs) — waits chunks 0-2; overlaps softmax chunk 3
    cudaStreamWaitEvent(0, evM[0], 0);
    cudaStreamWaitEvent(0, evM[1], 0);
    cudaStreamWaitEvent(0, evM[2], 0);
    pv_mma_kernel<<<dim3(8, 48), 256, PV_SMEM>>>(0);
    // pvB: bh 48..63 — waits chunk 3
    cudaStreamWaitEvent(0, evM[3], 0);
    pv_mma_kernel<<<dim3(8, 16), 256, PV_SMEM>>>(48);

    outproj_mma_kernel<<<dim3(8, 32), 256, OP_SMEM>>>(x, out);
    ln_kernel<<<4096, 256>>>(out, gamma, beta);
}

// round 9
// speedup vs baseline: 2.0408x; 1.0920x over previous
#include <cuda_runtime.h>
#include <cuda_fp16.h>
#include <math.h>
#include <stdint.h>

#define SEQ   1024
#define MEMN  1024
#define TT    2048
#define BATCH 4
#define NH    16
#define DH    64
#define DM    1024
#define BH    (BATCH*NH)   // 64

// ---------------- scratch (device globals, all fp16) ----------------
__device__ __half g_ac[(size_t)BH*SEQ*TT];
__device__ __half g_bd[(size_t)BH*SEQ*TT];

__device__ __half g_c [(size_t)8192*1024];
__device__ __half g_p [(size_t)8192*1024];
__device__ __half g_w [(size_t)4096*1024];
__device__ __half g_wo[(size_t)1024*1024];

__device__ __half g_qu[(size_t)BH*SEQ*DH];
__device__ __half g_qv[(size_t)BH*SEQ*DH];
__device__ __half g_k [(size_t)BH*TT*DH];
__device__ __half g_v [(size_t)BH*TT*DH];
__device__ __half g_r [(size_t)BH*TT*DH];

__device__ __half g_ph[(size_t)BH*SEQ*TT];
__device__ __half g_av[(size_t)SEQ*BATCH*DM];

// ---------------- helpers ----------------
__device__ __forceinline__ uint32_t smem_u32(const void* p){
    uint32_t a;
    asm("{ .reg .u64 t; cvta.to.shared.u64 t, %1; cvt.u32.u64 %0, t; }" : "=r"(a) : "l"(p));
    return a;
}
__device__ __forceinline__ void cp16(uint32_t s, const void* g){
    asm volatile("cp.async.cg.shared.global [%0], [%1], 16;" :: "r"(s), "l"(g));
}
#define CP_COMMIT() asm volatile("cp.async.commit_group;" ::: "memory")
#define CP_WAIT0()  asm volatile("cp.async.wait_group 0;" ::: "memory")

__device__ __forceinline__ void ldm4(uint32_t* r, uint32_t addr){
    asm volatile("ldmatrix.sync.aligned.m8n8.x4.shared.b16 {%0,%1,%2,%3}, [%4];"
        : "=r"(r[0]), "=r"(r[1]), "=r"(r[2]), "=r"(r[3]) : "r"(addr));
}
__device__ __forceinline__ void ldm4t(uint32_t* r, uint32_t addr){
    asm volatile("ldmatrix.sync.aligned.m8n8.x4.trans.shared.b16 {%0,%1,%2,%3}, [%4];"
        : "=r"(r[0]), "=r"(r[1]), "=r"(r[2]), "=r"(r[3]) : "r"(addr));
}
__device__ __forceinline__ void mma_f16(float* c, const uint32_t* a, uint32_t b0, uint32_t b1){
    asm volatile("mma.sync.aligned.m16n8k16.row.col.f32.f16.f16.f32 "
        "{%0,%1,%2,%3}, {%4,%5,%6,%7}, {%8,%9}, {%0,%1,%2,%3};"
        : "+f"(c[0]), "+f"(c[1]), "+f"(c[2]), "+f"(c[3])
        : "r"(a[0]), "r"(a[1]), "r"(a[2]), "r"(a[3]), "r"(b0), "r"(b1));
}
__device__ __forceinline__ uint4 pack8h(const float* v){
    __half2 a = __floats2half2_rn(v[0], v[1]);
    __half2 b = __floats2half2_rn(v[2], v[3]);
    __half2 c = __floats2half2_rn(v[4], v[5]);
    __half2 d = __floats2half2_rn(v[6], v[7]);
    uint4 r;
    r.x = *(uint32_t*)&a; r.y = *(uint32_t*)&b;
    r.z = *(uint32_t*)&c; r.w = *(uint32_t*)&d;
    return r;
}
__device__ __forceinline__ uint32_t packh2(float a, float b){
    __half2 h = __floats2half2_rn(a, b);
    return *(uint32_t*)&h;
}

__device__ __forceinline__ float warpReduceSum(float v){
    #pragma unroll
    for (int o = 16; o > 0; o >>= 1) v += __shfl_xor_sync(0xffffffffu, v, o);
    return v;
}
__device__ __forceinline__ float warpReduceMax(float v){
    #pragma unroll
    for (int o = 16; o > 0; o >>= 1) v = fmaxf(v, __shfl_xor_sync(0xffffffffu, v, o));
    return v;
}

// ---------------- kernel 0: fp32 -> fp16 conversion ----------------
__global__ __launch_bounds__(256) void conv_kernel(
    const float* __restrict__ x, const float* __restrict__ mem,
    const float* __restrict__ pos, const float* __restrict__ Wqkv,
    const float* __restrict__ Wrel, const float* __restrict__ Wo)
{
    const size_t u = (size_t)blockIdx.x * 256 + threadIdx.x;
    const float* src;
    __half* dst;
    size_t elem;
    if (u < 2097152) {
        elem = u * 4;
        const size_t row = elem >> 10, col = elem & 1023;
        src = (row < 4096) ? (mem + row*1024 + col) : (x + (row-4096)*1024 + col);
        dst = g_c + elem;
    } else if (u < 4194304) {
        elem = (u - 2097152) * 4;
        src = pos + elem;
        dst = g_p + elem;
    } else if (u < 5242880) {
        elem = (u - 4194304) * 4;
        const size_t row = elem >> 10, col = elem & 1023;
        src = (row < 3072) ? (Wqkv + row*1024 + col) : (Wrel + (row-3072)*1024 + col);
        dst = g_w + elem;
    } else {
        elem = (u - 5242880) * 4;
        src = Wo + elem;
        dst = g_wo + elem;
    }
    float4 v = *(const float4*)src;
    __half2 h01 = __floats2half2_rn(v.x, v.y);
    __half2 h23 = __floats2half2_rn(v.z, v.w);
    *(uint2*)dst = make_uint2(*(uint32_t*)&h01, *(uint32_t*)&h23);
}

// ---------------- kernel 1: fp16 projection GEMM (K-chunk 64) ----------------
#define PJ_BUF   36864
#define PJ_SMEM  73728   // 2 buffers; fp32 staging (67584) reuses the region

__global__ __launch_bounds__(256) void proj_mma_kernel(
    const float* __restrict__ pbu, const float* __restrict__ pbv)
{
    extern __shared__ __align__(128) char smem[];
    const uint32_t sbase = smem_u32(smem);
    const int tid = threadIdx.x, lane = tid & 31, wid = tid >> 5;
    const int bid = blockIdx.x;
    int n0, m0;
    if (bid < 256){ n0 = (bid & 7) * 128; m0 = 4096 + (bid >> 3) * 128; }
    else { const int b2 = bid - 256; n0 = 1024 + (b2 % 24) * 128; m0 = (b2 / 24) * 128; }

    const bool is_rel = (n0 >= 3072);
    const __half* Ap = (is_rel ? g_p : g_c) + (size_t)m0 * 1024;
    const __half* Bp = g_w + (size_t)n0 * 1024;

    const int wm = (wid & 3) * 32;
    const int wn = (wid >> 2) * 64;
    const int lsel = lane & 15;
    const int kof  = (lane < 16) ? 0 : 8;

    float acc[2][8][4];
    #pragma unroll
    for (int mt = 0; mt < 2; mt++)
        #pragma unroll
        for (int nt = 0; nt < 8; nt++)
            #pragma unroll
            for (int q = 0; q < 4; q++) acc[mt][nt][q] = 0.f;

    auto issue = [&](int c, int b){
        const int k0 = c * 64;
        const uint32_t sb = sbase + b * PJ_BUF;
        #pragma unroll
        for (int p = 0; p < 4; p++){
            const int u = p * 256 + tid;
            const int row = u >> 3, seg = u & 7;
            const size_t go = (size_t)row * 1024 + k0 + seg * 8;
            const uint32_t so = row * 144 + seg * 16;
            cp16(sb + so,         Ap + go);
            cp16(sb + 18432 + so, Bp + go);
        }
        CP_COMMIT();
    };

    issue(0, 0);
    for (int c = 0; c < 16; c++){
        CP_WAIT0();
        __syncthreads();
        if (c + 1 < 16) issue(c + 1, (c + 1) & 1);
        const uint32_t sb = sbase + (c & 1) * PJ_BUF;
        #pragma unroll
        for (int kk = 0; kk < 64; kk += 16){
            uint32_t ah[2][4], bh[4][4];
            #pragma unroll
            for (int mt = 0; mt < 2; mt++)
                ldm4(ah[mt], sb + (wm + mt*16 + lsel) * 144 + (kk + kof) * 2);
            #pragma unroll
            for (int g = 0; g < 4; g++)
                ldm4(bh[g], sb + 18432 + (wn + g*16 + lsel) * 144 + (kk + kof) * 2);
            #pragma unroll
            for (int mt = 0; mt < 2; mt++)
                #pragma unroll
                for (int nt = 0; nt < 8; nt++){
                    const int g = nt >> 1, s = nt & 1;
                    mma_f16(acc[mt][nt], ah[mt], bh[g][s], bh[g][s+2]);
                }
        }
        __syncthreads();
    }

    float* stg = (float*)smem;
    const int fr = lane >> 2, fc = (lane & 3) * 2;
    #pragma unroll
    for (int mt = 0; mt < 2; mt++)
        #pragma unroll
        for (int nt = 0; nt < 8; nt++){
            const int col = wn + nt*8 + fc;
            const int row0 = wm + mt*16 + fr;
            stg[row0*132 + col]       = acc[mt][nt][0];
            stg[row0*132 + col + 1]   = acc[mt][nt][1];
            stg[(row0+8)*132 + col]   = acc[mt][nt][2];
            stg[(row0+8)*132 + col+1] = acc[mt][nt][3];
        }
    __syncthreads();

    const int rr = tid >> 1, hf = tid & 1;
    const int m = m0 + rr;
    const int t_ = m >> 2, b_ = m & 3;
    const float* src = stg + rr * 132 + hf * 64;
    const int nbase = n0 + hf * 64;
    const int cat = n0 >> 10;
    if (cat == 0){
        const int i = t_ - MEMN;
        const int h = nbase >> 6;
        const size_t off = (((size_t)(b_*NH + h))*SEQ + i)*DH;
        #pragma unroll
        for (int s = 0; s < 8; s++){
            float qu8[8], qv8[8];
            #pragma unroll
            for (int e = 0; e < 8; e++){
                const float v = src[s*8 + e];
                qu8[e] = v + pbu[nbase + s*8 + e];
                qv8[e] = v + pbv[nbase + s*8 + e];
            }
            *(uint4*)(g_qu + off + s*8) = pack8h(qu8);
            *(uint4*)(g_qv + off + s*8) = pack8h(qv8);
        }
    } else {
        const int nn = nbase - cat*1024;
        const int h = nn >> 6;
        __half* bptr = (cat == 1) ? g_k : (cat == 2) ? g_v : g_r;
        const size_t off = (((size_t)(b_*NH + h))*TT + t_)*DH;
        #pragma unroll
        for (int s = 0; s < 8; s++)
            *(uint4*)(bptr + off + s*8) = pack8h(src + s*8);
    }
}

// ---------------- kernel 2: fp16 score GEMMs, A-persistent j-loop ----------------
// grid (4, 8, 2*CHBH): x = j-group (4 j-tiles each), y = i-tile, z = bh*2+which
// SMEM: A @0 (18432), B bufs @18432/@36864 (18432 each), fp16 staging @55296 (34816)
#define SC_SMEM 90112

__global__ __launch_bounds__(256) void score_mma_kernel(int bh0)
{
    extern __shared__ __align__(128) char smem[];
    const uint32_t sbase = smem_u32(smem);
    const int tid = threadIdx.x, lane = tid & 31, wid = tid >> 5;
    const int z = blockIdx.z;
    const int bh = bh0 + (z >> 1), which = z & 1;
    const __half* Ap = (which ? g_qv : g_qu) + (size_t)bh * SEQ * DH;
    const __half* Bp = (which ? g_r  : g_k ) + (size_t)bh * TT  * DH;
    __half* Ob = (which ? g_bd : g_ac) + (size_t)bh * SEQ * TT;
    const int i0 = blockIdx.y * 128;
    const int jg = blockIdx.x * 4;   // first j-tile index

    const int wm = (wid & 3) * 32;
    const int wn = (wid >> 2) * 64;
    const int lsel = lane & 15;
    const int kof  = (lane < 16) ? 0 : 8;

    // issue A (once) + B tile jt into buffer b
    auto issueB = [&](int jt, int b){
        const int j0 = (jg + jt) * 128;
        const uint32_t sb = sbase + 18432 + b * 18432;
        #pragma unroll
        for (int p = 0; p < 4; p++){
            const int u = p * 256 + tid;
            const int row = u >> 3, seg = u & 7;
            cp16(sb + row * 144 + seg * 16, Bp + (size_t)(j0 + row) * DH + seg * 8);
        }
        CP_COMMIT();
    };

    // A + B0 as first group
    {
        #pragma unroll
        for (int p = 0; p < 4; p++){
            const int u = p * 256 + tid;
            const int row = u >> 3, seg = u & 7;
            cp16(sbase + row * 144 + seg * 16, Ap + (size_t)(i0 + row) * DH + seg * 8);
        }
        issueB(0, 0);   // commits A+B0 together
    }

    __half* stg = (__half*)(smem + 55296);   // 128 rows x 136 halves (272 B rows)

    for (int jt = 0; jt < 4; jt++){
        float acc[2][8][4];
        #pragma unroll
        for (int mt = 0; mt < 2; mt++)
            #pragma unroll
            for (int nt = 0; nt < 8; nt++)
                #pragma unroll
                for (int q = 0; q < 4; q++) acc[mt][nt][q] = 0.f;

        CP_WAIT0();
        __syncthreads();
        if (jt + 1 < 4) issueB(jt + 1, (jt + 1) & 1);
        const uint32_t sbB = sbase + 18432 + (jt & 1) * 18432;

        #pragma unroll
        for (int kk = 0; kk < 64; kk += 16){
            uint32_t ah[2][4], bh[4][4];
            #pragma unroll
            for (int mt = 0; mt < 2; mt++)
                ldm4(ah[mt], sbase + (wm + mt*16 + lsel) * 144 + (kk + kof) * 2);
            #pragma unroll
            for (int g = 0; g < 4; g++)
                ldm4(bh[g], sbB + (wn + g*16 + lsel) * 144 + (kk + kof) * 2);
            #pragma unroll
            for (int mt = 0; mt < 2; mt++)
                #pragma unroll
                for (int nt = 0; nt < 8; nt++){
                    const int g = nt >> 1, s = nt & 1;
                    mma_f16(acc[mt][nt], ah[mt], bh[g][s], bh[g][s+2]);
                }
        }

        // stage fp16 + coalesced write
        __syncthreads();
        const int fr = lane >> 2, fc = (lane & 3) * 2;
        #pragma unroll
        for (int mt = 0; mt < 2; mt++)
            #pragma unroll
            for (int nt = 0; nt < 8; nt++){
                const int col = wn + nt*8 + fc;
                const int row0 = wm + mt*16 + fr;
                *(uint32_t*)(stg + row0*136 + col)     = packh2(acc[mt][nt][0], acc[mt][nt][1]);
                *(uint32_t*)(stg + (row0+8)*136 + col) = packh2(acc[mt][nt][2], acc[mt][nt][3]);
            }
        __syncthreads();
        const int rr = tid >> 1, hf = tid & 1;
        const __half* srcp = stg + rr * 136 + hf * 64;
        __half* orow = Ob + (size_t)(i0 + rr) * TT + (jg + jt) * 128 + hf * 64;
        #pragma unroll
        for (int s = 0; s < 8; s++)
            *(uint4*)(orow + s*8) = *(const uint4*)(srcp + s*8);
        __syncthreads();
    }
}

// ---------------- kernel 3: rel-shift + softmax -> fp16 probs ----------------
__global__ __launch_bounds__(256) void softmax_shift_kernel(int bh0)
{
    const int i  = blockIdx.x;
    const int bh = bh0 + blockIdx.y;
    const int t  = threadIdx.x;
    const size_t rowoff = ((size_t)bh*SEQ + i) * TT;
    const __half* ac = g_ac + rowoff;
    const __half* bd0 = g_bd + rowoff;
    const __half* bd1 = bd0 + TT;

    float sv[8];
    float lmax = -INFINITY;
    #pragma unroll
    for (int q = 0; q < 8; q++){
        const int j = q*256 + t;
        const int delta = j - i;
        float bd;
        if (delta <= 1024)      bd = __half2float(bd0[delta + 1023]);
        else if (delta == 1025) bd = 0.f;
        else                    bd = __half2float(bd1[delta - 1026]);
        const float s = (__half2float(ac[j]) + bd) * 0.125f;
        sv[q] = s;
        lmax = fmaxf(lmax, s);
    }
    __shared__ float sh[8];
    float wmax = warpReduceMax(lmax);
    if ((t & 31) == 0) sh[t >> 5] = wmax;
    __syncthreads();
    float mx = sh[0];
    #pragma unroll
    for (int w = 1; w < 8; w++) mx = fmaxf(mx, sh[w]);
    __syncthreads();

    float lsum = 0.f;
    #pragma unroll
    for (int q = 0; q < 8; q++){
        const float p = __expf(sv[q] - mx);
        sv[q] = p;
        lsum += p;
    }
    float wsum = warpReduceSum(lsum);
    if ((t & 31) == 0) sh[t >> 5] = wsum;
    __syncthreads();
    float sum = 0.f;
    #pragma unroll
    for (int w = 0; w < 8; w++) sum += sh[w];
    const float sinv = 1.f / sum;

    __half* ph = g_ph + rowoff;
    #pragma unroll
    for (int q = 0; q < 8; q++){
        const int j = q*256 + t;
        ph[j] = __float2half_rn(sv[q] * sinv);
    }
}

// ---------------- kernel 4: fp16 PV GEMM ----------------
#define PV_BUF   14848
#define PV_SMEM  34816

__global__ __launch_bounds__(256) void pv_mma_kernel(int bh0)
{
    extern __shared__ __align__(128) char smem[];
    const uint32_t sbase = smem_u32(smem);
    const int tid = threadIdx.x, lane = tid & 31, wid = tid >> 5;
    const int bh = bh0 + blockIdx.y;
    const int i0 = blockIdx.x * 128;
    const __half* Pp = g_ph + (size_t)bh*SEQ*TT + (size_t)i0*TT;
    const __half* Vp = g_v + (size_t)bh*TT*DH;

    const int wm = (wid & 3) * 32;
    const int wn = (wid >> 2) * 32;
    const int lsel = lane & 15;
    const int kof  = (lane < 16) ? 0 : 8;
    const int tcol = (lane >> 4) * 8;

    float acc[2][4][4];
    #pragma unroll
    for (int mt = 0; mt < 2; mt++)
        #pragma unroll
        for (int nt = 0; nt < 4; nt++)
            #pragma unroll
            for (int q = 0; q < 4; q++) acc[mt][nt][q] = 0.f;

    auto issue = [&](int c, int b){
        const int k0 = c * 32;
        const uint32_t sb = sbase + b * PV_BUF;
        #pragma unroll
        for (int p = 0; p < 2; p++){
            const int u = p * 256 + tid;
            const int row = u >> 2, seg = u & 3;
            cp16(sb + row * 80 + seg * 16, Pp + (size_t)row * TT + k0 + seg * 8);
        }
        {
            const int row = tid >> 3, seg = tid & 7;
            cp16(sb + 10240 + row * 144 + seg * 16, Vp + (size_t)(k0 + row) * DH + seg * 8);
        }
        CP_COMMIT();
    };

    issue(0, 0);
    for (int c = 0; c < 64; c++){
        CP_WAIT0();
        __syncthreads();
        if (c + 1 < 64) issue(c + 1, (c + 1) & 1);
        const uint32_t sb = sbase + (c & 1) * PV_BUF;
        #pragma unroll
        for (int kk = 0; kk < 32; kk += 16){
            uint32_t ph[2][4], vh[2][4];
            #pragma unroll
            for (int mt = 0; mt < 2; mt++)
                ldm4(ph[mt], sb + (wm + mt*16 + lsel) * 80 + (kk + kof) * 2);
            #pragma unroll
            for (int g = 0; g < 2; g++)
                ldm4t(vh[g], sb + 10240 + (kk + lsel) * 144 + (wn + g*16 + tcol) * 2);
            #pragma unroll
            for (int mt = 0; mt < 2; mt++)
                #pragma unroll
                for (int nt = 0; nt < 4; nt++){
                    const int g = nt >> 1, s = nt & 1;
                    mma_f16(acc[mt][nt], ph[mt], vh[g][2*s], vh[g][2*s+1]);
                }
        }
    }

    __syncthreads();
    float* stg = (float*)smem;
    const int fr = lane >> 2, fc = (lane & 3) * 2;
    #pragma unroll
    for (int mt = 0; mt < 2; mt++)
        #pragma unroll
        for (int nt = 0; nt < 4; nt++){
            const int col = wn + nt*8 + fc;
            const int row0 = wm + mt*16 + fr;
            stg[row0*68 + col]       = acc[mt][nt][0];
            stg[row0*68 + col + 1]   = acc[mt][nt][1];
            stg[(row0+8)*68 + col]   = acc[mt][nt][2];
            stg[(row0+8)*68 + col+1] = acc[mt][nt][3];
        }
    __syncthreads();
    const int rr = tid >> 1, hf = tid & 1;
    const int b = bh >> 4, h = bh & 15;
    const int i = i0 + rr;
    const float* src = stg + rr * 68 + hf * 32;
    const size_t off = ((size_t)i*BATCH + b)*DM + h*DH + hf*32;
    #pragma unroll
    for (int s = 0; s < 4; s++)
        *(uint4*)(g_av + off + s*8) = pack8h(src + s*8);
}

// ---------------- kernel 5: fp16 out projection + residual ----------------
#define OP_BUF   20480
#define OP_SMEM  67584

__global__ __launch_bounds__(256) void outproj_mma_kernel(const float* __restrict__ x,
                                                          float* __restrict__ out)
{
    extern __shared__ __align__(128) char smem[];
    const uint32_t sbase = smem_u32(smem);
    const int tid = threadIdx.x, lane = tid & 31, wid = tid >> 5;
    const int n0 = blockIdx.x * 128;
    const int m0 = blockIdx.y * 128;
    const __half* Ap = g_av + (size_t)m0 * 1024;
    const __half* Bp = g_wo + (size_t)n0 * 1024;

    const int wm = (wid & 3) * 32;
    const int wn = (wid >> 2) * 64;
    const int lsel = lane & 15;
    const int kof  = (lane < 16) ? 0 : 8;

    float acc[2][8][4];
    #pragma unroll
    for (int mt = 0; mt < 2; mt++)
        #pragma unroll
        for (int nt = 0; nt < 8; nt++)
            #pragma unroll
            for (int q = 0; q < 4; q++) acc[mt][nt][q] = 0.f;

    auto issue = [&](int c, int b){
        const int k0 = c * 32;
        const uint32_t sb = sbase + b * OP_BUF;
        #pragma unroll
        for (int p = 0; p < 2; p++){
            const int u = p * 256 + tid;
            const int row = u >> 2, seg = u & 3;
            const size_t go = (size_t)row * 1024 + k0 + seg * 8;
            const uint32_t so = row * 80 + seg * 16;
            cp16(sb + so,         Ap + go);
            cp16(sb + 10240 + so, Bp + go);
        }
        CP_COMMIT();
    };

    issue(0, 0);
    for (int c = 0; c < 32; c++){
        CP_WAIT0();
        __syncthreads();
        if (c + 1 < 32) issue(c + 1, (c + 1) & 1);
        const uint32_t sb = sbase + (c & 1) * OP_BUF;
        #pragma unroll
        for (int kk = 0; kk < 32; kk += 16){
            uint32_t ah[2][4], bh[4][4];
            #pragma unroll
            for (int mt = 0; mt < 2; mt++)
                ldm4(ah[mt], sb + (wm + mt*16 + lsel) * 80 + (kk + kof) * 2);
            #pragma unroll
            for (int g = 0; g < 4; g++)
                ldm4(bh[g], sb + 10240 + (wn + g*16 + lsel) * 80 + (kk + kof) * 2);
            #pragma unroll
            for (int mt = 0; mt < 2; mt++)
                #pragma unroll
                for (int nt = 0; nt < 8; nt++){
                    const int g = nt >> 1, s = nt & 1;
                    mma_f16(acc[mt][nt], ah[mt], bh[g][s], bh[g][s+2]);
                }
        }
        __syncthreads();
    }

    float* stg = (float*)smem;
    const int fr = lane >> 2, fc = (lane & 3) * 2;
    #pragma unroll
    for (int mt = 0; mt < 2; mt++)
        #pragma unroll
        for (int nt = 0; nt < 8; nt++){
            const int col = wn + nt*8 + fc;
            const int row0 = wm + mt*16 + fr;
            stg[row0*132 + col]       = acc[mt][nt][0];
            stg[row0*132 + col + 1]   = acc[mt][nt][1];
            stg[(row0+8)*132 + col]   = acc[mt][nt][2];
            stg[(row0+8)*132 + col+1] = acc[mt][nt][3];
        }
    __syncthreads();
    const int rr = tid >> 1, hf = tid & 1;
    const int m = m0 + rr;
    const float* src = stg + rr * 132 + hf * 64;
    const float* xr = x + (size_t)m*DM + n0 + hf*64;
    float* orow = out + (size_t)m*DM + n0 + hf*64;
    #pragma unroll
    for (int s = 0; s < 16; s++){
        float4 v = *(const float4*)(src + s*4);
        float4 xx = *(const float4*)(xr + s*4);
        *(float4*)(orow + s*4) = make_float4(v.x+xx.x, v.y+xx.y, v.z+xx.z, v.w+xx.w);
    }
}

// ---------------- kernel 6: LayerNorm ----------------
__global__ __launch_bounds__(256) void ln_kernel(float* __restrict__ out,
                                                 const float* __restrict__ gamma,
                                                 const float* __restrict__ beta)
{
    const int row = blockIdx.x;
    float* y = out + (size_t)row * DM;
    const int t = threadIdx.x;
    float v[4];
    float s = 0.f, sq = 0.f;
    #pragma unroll
    for (int q = 0; q < 4; q++){
        v[q] = y[q*256 + t];
        s += v[q];
        sq += v[q]*v[q];
    }
    __shared__ float sh[16];
    float ws = warpReduceSum(s);
    float wq = warpReduceSum(sq);
    if ((t & 31) == 0){ sh[t>>5] = ws; sh[8 + (t>>5)] = wq; }
    __syncthreads();
    s = 0.f; sq = 0.f;
    #pragma unroll
    for (int w = 0; w < 8; w++){ s += sh[w]; sq += sh[8+w]; }
    const float mu = s * (1.f/1024.f);
    const float var = sq * (1.f/1024.f) - mu*mu;
    const float rstd = rsqrtf(var + 1e-5f);
    #pragma unroll
    for (int q = 0; q < 4; q++){
        const int d = q*256 + t;
        y[d] = gamma[d] * ((v[q] - mu) * rstd) + beta[d];
    }
}

// ---------------- launch ----------------
#define NCHUNK 4
#define CHBH   16

extern "C" void kernel_launch(void* const* d_in, const int* in_sizes, int n_in,
                              void* d_out, int out_size)
{
    const float* x     = (const float*)d_in[0];
    const float* mem   = (const float*)d_in[1];
    const float* pos   = (const float*)d_in[2];
    const float* pbu   = (const float*)d_in[3];
    const float* pbv   = (const float*)d_in[4];
    const float* Wqkv  = (const float*)d_in[5];
    const float* Wrel  = (const float*)d_in[6];
    const float* Wo    = (const float*)d_in[7];
    const float* gamma = (const float*)d_in[8];
    const float* beta  = (const float*)d_in[9];
    float* out = (float*)d_out;

    static cudaStream_t s1 = nullptr;
    static cudaEvent_t evS[NCHUNK], evM[NCHUNK];
    if (!s1){
        cudaStreamCreateWithFlags(&s1, cudaStreamNonBlocking);
        for (int c = 0; c < NCHUNK; c++){
            cudaEventCreateWithFlags(&evS[c], cudaEventDisableTiming);
            cudaEventCreateWithFlags(&evM[c], cudaEventDisableTiming);
        }
        cudaFuncSetAttribute(proj_mma_kernel,    cudaFuncAttributeMaxDynamicSharedMemorySize, PJ_SMEM);
        cudaFuncSetAttribute(score_mma_kernel,   cudaFuncAttributeMaxDynamicSharedMemorySize, SC_SMEM);
        cudaFuncSetAttribute(pv_mma_kernel,      cudaFuncAttributeMaxDynamicSharedMemorySize, PV_SMEM);
        cudaFuncSetAttribute(outproj_mma_kernel, cudaFuncAttributeMaxDynamicSharedMemorySize, OP_SMEM);
    }

    conv_kernel<<<21504, 256>>>(x, mem, pos, Wqkv, Wrel, Wo);
    proj_mma_kernel<<<1792, 256, PJ_SMEM>>>(pbu, pbv);

    for (int c = 0; c < NCHUNK; c++){
        score_mma_kernel<<<dim3(4, 8, 2*CHBH), 256, SC_SMEM>>>(c * CHBH);
        cudaEventRecord(evS[c], 0);
        cudaStreamWaitEvent(s1, evS[c], 0);
        softmax_shift_kernel<<<dim3(1024, CHBH), 256, 0, s1>>>(c * CHBH);
        cudaEventRecord(evM[c], s1);
    }
    cudaStreamWaitEvent(0, evM[0], 0);
    cudaStreamWaitEvent(0, evM[1], 0);
    cudaStreamWaitEvent(0, evM[2], 0);
    pv_mma_kernel<<<dim3(8, 48), 256, PV_SMEM>>>(0);
    cudaStreamWaitEvent(0, evM[3], 0);
    pv_mma_kernel<<<dim3(8, 16), 256, PV_SMEM>>>(48);

    outproj_mma_kernel<<<dim3(8, 32), 256, OP_SMEM>>>(x, out);
    ln_kernel<<<4096, 256>>>(out, gamma, beta);
}

// round 10
// speedup vs baseline: 2.0762x; 1.0174x over previous
#include <cuda_runtime.h>
#include <cuda_fp16.h>
#include <math.h>
#include <stdint.h>

#define SEQ   1024
#define MEMN  1024
#define TT    2048
#define BATCH 4
#define NH    16
#define DH    64
#define DM    1024
#define BH    (BATCH*NH)   // 64

// ---------------- scratch (device globals, all fp16) ----------------
__device__ __half g_ac[(size_t)BH*SEQ*TT];
__device__ __half g_bd[(size_t)BH*SEQ*TT];

__device__ __half g_c [(size_t)8192*1024];
__device__ __half g_p [(size_t)8192*1024];
__device__ __half g_w [(size_t)4096*1024];
__device__ __half g_wo[(size_t)1024*1024];

__device__ __half g_qu[(size_t)BH*SEQ*DH];
__device__ __half g_qv[(size_t)BH*SEQ*DH];
__device__ __half g_k [(size_t)BH*TT*DH];
__device__ __half g_v [(size_t)BH*TT*DH];
__device__ __half g_r [(size_t)BH*TT*DH];

__device__ __half g_ph[(size_t)BH*SEQ*TT];
__device__ __half g_av[(size_t)SEQ*BATCH*DM];

// ---------------- helpers ----------------
__device__ __forceinline__ uint32_t smem_u32(const void* p){
    uint32_t a;
    asm("{ .reg .u64 t; cvta.to.shared.u64 t, %1; cvt.u32.u64 %0, t; }" : "=r"(a) : "l"(p));
    return a;
}
__device__ __forceinline__ void cp16(uint32_t s, const void* g){
    asm volatile("cp.async.cg.shared.global [%0], [%1], 16;" :: "r"(s), "l"(g));
}
#define CP_COMMIT() asm volatile("cp.async.commit_group;" ::: "memory")
#define CP_WAIT0()  asm volatile("cp.async.wait_group 0;" ::: "memory")

__device__ __forceinline__ void ldm4(uint32_t* r, uint32_t addr){
    asm volatile("ldmatrix.sync.aligned.m8n8.x4.shared.b16 {%0,%1,%2,%3}, [%4];"
        : "=r"(r[0]), "=r"(r[1]), "=r"(r[2]), "=r"(r[3]) : "r"(addr));
}
__device__ __forceinline__ void ldm4t(uint32_t* r, uint32_t addr){
    asm volatile("ldmatrix.sync.aligned.m8n8.x4.trans.shared.b16 {%0,%1,%2,%3}, [%4];"
        : "=r"(r[0]), "=r"(r[1]), "=r"(r[2]), "=r"(r[3]) : "r"(addr));
}
__device__ __forceinline__ void mma_f16(float* c, const uint32_t* a, uint32_t b0, uint32_t b1){
    asm volatile("mma.sync.aligned.m16n8k16.row.col.f32.f16.f16.f32 "
        "{%0,%1,%2,%3}, {%4,%5,%6,%7}, {%8,%9}, {%0,%1,%2,%3};"
        : "+f"(c[0]), "+f"(c[1]), "+f"(c[2]), "+f"(c[3])
        : "r"(a[0]), "r"(a[1]), "r"(a[2]), "r"(a[3]), "r"(b0), "r"(b1));
}
__device__ __forceinline__ uint4 pack8h(const float* v){
    __half2 a = __floats2half2_rn(v[0], v[1]);
    __half2 b = __floats2half2_rn(v[2], v[3]);
    __half2 c = __floats2half2_rn(v[4], v[5]);
    __half2 d = __floats2half2_rn(v[6], v[7]);
    uint4 r;
    r.x = *(uint32_t*)&a; r.y = *(uint32_t*)&b;
    r.z = *(uint32_t*)&c; r.w = *(uint32_t*)&d;
    return r;
}
__device__ __forceinline__ uint32_t packh2(float a, float b){
    __half2 h = __floats2half2_rn(a, b);
    return *(uint32_t*)&h;
}

__device__ __forceinline__ float warpReduceSum(float v){
    #pragma unroll
    for (int o = 16; o > 0; o >>= 1) v += __shfl_xor_sync(0xffffffffu, v, o);
    return v;
}

// ---------------- kernel 0: fp32 -> fp16 conversion ----------------
__global__ __launch_bounds__(256) void conv_kernel(
    const float* __restrict__ x, const float* __restrict__ mem,
    const float* __restrict__ pos, const float* __restrict__ Wqkv,
    const float* __restrict__ Wrel, const float* __restrict__ Wo)
{
    const size_t u = (size_t)blockIdx.x * 256 + threadIdx.x;
    const float* src;
    __half* dst;
    size_t elem;
    if (u < 2097152) {
        elem = u * 4;
        const size_t row = elem >> 10, col = elem & 1023;
        src = (row < 4096) ? (mem + row*1024 + col) : (x + (row-4096)*1024 + col);
        dst = g_c + elem;
    } else if (u < 4194304) {
        elem = (u - 2097152) * 4;
        src = pos + elem;
        dst = g_p + elem;
    } else if (u < 5242880) {
        elem = (u - 4194304) * 4;
        const size_t row = elem >> 10, col = elem & 1023;
        src = (row < 3072) ? (Wqkv + row*1024 + col) : (Wrel + (row-3072)*1024 + col);
        dst = g_w + elem;
    } else {
        elem = (u - 5242880) * 4;
        src = Wo + elem;
        dst = g_wo + elem;
    }
    float4 v = *(const float4*)src;
    __half2 h01 = __floats2half2_rn(v.x, v.y);
    __half2 h23 = __floats2half2_rn(v.z, v.w);
    *(uint2*)dst = make_uint2(*(uint32_t*)&h01, *(uint32_t*)&h23);
}

// ---------------- kernel 1: fp16 projection GEMM (K-chunk 64) ----------------
#define PJ_BUF   36864
#define PJ_SMEM  73728

__global__ __launch_bounds__(256) void proj_mma_kernel(
    const float* __restrict__ pbu, const float* __restrict__ pbv)
{
    extern __shared__ __align__(128) char smem[];
    const uint32_t sbase = smem_u32(smem);
    const int tid = threadIdx.x, lane = tid & 31, wid = tid >> 5;
    const int bid = blockIdx.x;
    int n0, m0;
    if (bid < 256){ n0 = (bid & 7) * 128; m0 = 4096 + (bid >> 3) * 128; }
    else { const int b2 = bid - 256; n0 = 1024 + (b2 % 24) * 128; m0 = (b2 / 24) * 128; }

    const bool is_rel = (n0 >= 3072);
    const __half* Ap = (is_rel ? g_p : g_c) + (size_t)m0 * 1024;
    const __half* Bp = g_w + (size_t)n0 * 1024;

    const int wm = (wid & 3) * 32;
    const int wn = (wid >> 2) * 64;
    const int lsel = lane & 15;
    const int kof  = (lane < 16) ? 0 : 8;

    float acc[2][8][4];
    #pragma unroll
    for (int mt = 0; mt < 2; mt++)
        #pragma unroll
        for (int nt = 0; nt < 8; nt++)
            #pragma unroll
            for (int q = 0; q < 4; q++) acc[mt][nt][q] = 0.f;

    auto issue = [&](int c, int b){
        const int k0 = c * 64;
        const uint32_t sb = sbase + b * PJ_BUF;
        #pragma unroll
        for (int p = 0; p < 4; p++){
            const int u = p * 256 + tid;
            const int row = u >> 3, seg = u & 7;
            const size_t go = (size_t)row * 1024 + k0 + seg * 8;
            const uint32_t so = row * 144 + seg * 16;
            cp16(sb + so,         Ap + go);
            cp16(sb + 18432 + so, Bp + go);
        }
        CP_COMMIT();
    };

    issue(0, 0);
    for (int c = 0; c < 16; c++){
        CP_WAIT0();
        __syncthreads();
        if (c + 1 < 16) issue(c + 1, (c + 1) & 1);
        const uint32_t sb = sbase + (c & 1) * PJ_BUF;
        #pragma unroll
        for (int kk = 0; kk < 64; kk += 16){
            uint32_t ah[2][4], bh[4][4];
            #pragma unroll
            for (int mt = 0; mt < 2; mt++)
                ldm4(ah[mt], sb + (wm + mt*16 + lsel) * 144 + (kk + kof) * 2);
            #pragma unroll
            for (int g = 0; g < 4; g++)
                ldm4(bh[g], sb + 18432 + (wn + g*16 + lsel) * 144 + (kk + kof) * 2);
            #pragma unroll
            for (int mt = 0; mt < 2; mt++)
                #pragma unroll
                for (int nt = 0; nt < 8; nt++){
                    const int g = nt >> 1, s = nt & 1;
                    mma_f16(acc[mt][nt], ah[mt], bh[g][s], bh[g][s+2]);
                }
        }
    }

    __syncthreads();
    float* stg = (float*)smem;
    const int fr = lane >> 2, fc = (lane & 3) * 2;
    #pragma unroll
    for (int mt = 0; mt < 2; mt++)
        #pragma unroll
        for (int nt = 0; nt < 8; nt++){
            const int col = wn + nt*8 + fc;
            const int row0 = wm + mt*16 + fr;
            stg[row0*132 + col]       = acc[mt][nt][0];
            stg[row0*132 + col + 1]   = acc[mt][nt][1];
            stg[(row0+8)*132 + col]   = acc[mt][nt][2];
            stg[(row0+8)*132 + col+1] = acc[mt][nt][3];
        }
    __syncthreads();

    const int rr = tid >> 1, hf = tid & 1;
    const int m = m0 + rr;
    const int t_ = m >> 2, b_ = m & 3;
    const float* src = stg + rr * 132 + hf * 64;
    const int nbase = n0 + hf * 64;
    const int cat = n0 >> 10;
    if (cat == 0){
        const int i = t_ - MEMN;
        const int h = nbase >> 6;
        const size_t off = (((size_t)(b_*NH + h))*SEQ + i)*DH;
        #pragma unroll
        for (int s = 0; s < 8; s++){
            float qu8[8], qv8[8];
            #pragma unroll
            for (int e = 0; e < 8; e++){
                const float v = src[s*8 + e];
                qu8[e] = v + pbu[nbase + s*8 + e];
                qv8[e] = v + pbv[nbase + s*8 + e];
            }
            *(uint4*)(g_qu + off + s*8) = pack8h(qu8);
            *(uint4*)(g_qv + off + s*8) = pack8h(qv8);
        }
    } else {
        const int nn = nbase - cat*1024;
        const int h = nn >> 6;
        __half* bptr = (cat == 1) ? g_k : (cat == 2) ? g_v : g_r;
        const size_t off = (((size_t)(b_*NH + h))*TT + t_)*DH;
        #pragma unroll
        for (int s = 0; s < 8; s++)
            *(uint4*)(bptr + off + s*8) = pack8h(src + s*8);
    }
}

// ---------------- kernel 2: fp16 score GEMMs, A-persistent 8-j-tile loop ----------------
// grid (2, 8, 2*CHBH); SMEM: A @0 (18432), B bufs @18432/@36864, fp16 staging @55296
#define SC_SMEM 90112

__global__ __launch_bounds__(256) void score_mma_kernel(int bh0)
{
    extern __shared__ __align__(128) char smem[];
    const uint32_t sbase = smem_u32(smem);
    const int tid = threadIdx.x, lane = tid & 31, wid = tid >> 5;
    const int z = blockIdx.z;
    const int bh = bh0 + (z >> 1), which = z & 1;
    const __half* Ap = (which ? g_qv : g_qu) + (size_t)bh * SEQ * DH;
    const __half* Bp = (which ? g_r  : g_k ) + (size_t)bh * TT  * DH;
    __half* Ob = (which ? g_bd : g_ac) + (size_t)bh * SEQ * TT;
    const int i0 = blockIdx.y * 128;
    const int jg = blockIdx.x * 8;

    const int wm = (wid & 3) * 32;
    const int wn = (wid >> 2) * 64;
    const int lsel = lane & 15;
    const int kof  = (lane < 16) ? 0 : 8;

    auto issueB = [&](int jt, int b){
        const int j0 = (jg + jt) * 128;
        const uint32_t sb = sbase + 18432 + b * 18432;
        #pragma unroll
        for (int p = 0; p < 4; p++){
            const int u = p * 256 + tid;
            const int row = u >> 3, seg = u & 7;
            cp16(sb + row * 144 + seg * 16, Bp + (size_t)(j0 + row) * DH + seg * 8);
        }
        CP_COMMIT();
    };

    {
        #pragma unroll
        for (int p = 0; p < 4; p++){
            const int u = p * 256 + tid;
            const int row = u >> 3, seg = u & 7;
            cp16(sbase + row * 144 + seg * 16, Ap + (size_t)(i0 + row) * DH + seg * 8);
        }
        issueB(0, 0);
    }

    __half* stg = (__half*)(smem + 55296);

    for (int jt = 0; jt < 8; jt++){
        float acc[2][8][4];
        #pragma unroll
        for (int mt = 0; mt < 2; mt++)
            #pragma unroll
            for (int nt = 0; nt < 8; nt++)
                #pragma unroll
                for (int q = 0; q < 4; q++) acc[mt][nt][q] = 0.f;

        CP_WAIT0();
        __syncthreads();
        if (jt + 1 < 8) issueB(jt + 1, (jt + 1) & 1);
        const uint32_t sbB = sbase + 18432 + (jt & 1) * 18432;

        #pragma unroll
        for (int kk = 0; kk < 64; kk += 16){
            uint32_t ah[2][4], bh[4][4];
            #pragma unroll
            for (int mt = 0; mt < 2; mt++)
                ldm4(ah[mt], sbase + (wm + mt*16 + lsel) * 144 + (kk + kof) * 2);
            #pragma unroll
            for (int g = 0; g < 4; g++)
                ldm4(bh[g], sbB + (wn + g*16 + lsel) * 144 + (kk + kof) * 2);
            #pragma unroll
            for (int mt = 0; mt < 2; mt++)
                #pragma unroll
                for (int nt = 0; nt < 8; nt++){
                    const int g = nt >> 1, s = nt & 1;
                    mma_f16(acc[mt][nt], ah[mt], bh[g][s], bh[g][s+2]);
                }
        }

        __syncthreads();
        const int fr = lane >> 2, fc = (lane & 3) * 2;
        #pragma unroll
        for (int mt = 0; mt < 2; mt++)
            #pragma unroll
            for (int nt = 0; nt < 8; nt++){
                const int col = wn + nt*8 + fc;
                const int row0 = wm + mt*16 + fr;
                *(uint32_t*)(stg + row0*136 + col)     = packh2(acc[mt][nt][0], acc[mt][nt][1]);
                *(uint32_t*)(stg + (row0+8)*136 + col) = packh2(acc[mt][nt][2], acc[mt][nt][3]);
            }
        __syncthreads();
        const int rr = tid >> 1, hf = tid & 1;
        const __half* srcp = stg + rr * 136 + hf * 64;
        __half* orow = Ob + (size_t)(i0 + rr) * TT + (jg + jt) * 128 + hf * 64;
        #pragma unroll
        for (int s = 0; s < 8; s++)
            *(uint4*)(orow + s*8) = *(const uint4*)(srcp + s*8);
        __syncthreads();
    }
}

// ---------------- kernel 3: rel-shift + softmax (no max pass; scores bounded) ----------------
__global__ __launch_bounds__(256) void softmax_shift_kernel(int bh0)
{
    const int i  = blockIdx.x;
    const int bh = bh0 + blockIdx.y;
    const int t  = threadIdx.x;
    const size_t rowoff = ((size_t)bh*SEQ + i) * TT;
    const __half* ac = g_ac + rowoff;
    const __half* bd0 = g_bd + rowoff;
    const __half* bd1 = bd0 + TT;

    float sv[8];
    float lsum = 0.f;
    #pragma unroll
    for (int q = 0; q < 8; q++){
        const int j = q*256 + t;
        const int delta = j - i;
        float bd;
        if (delta <= 1024)      bd = __half2float(bd0[delta + 1023]);
        else if (delta == 1025) bd = 0.f;
        else                    bd = __half2float(bd1[delta - 1026]);
        const float s = (__half2float(ac[j]) + bd) * 0.125f;
        const float p = __expf(s);
        sv[q] = p;
        lsum += p;
    }
    __shared__ float sh[8];
    float wsum = warpReduceSum(lsum);
    if ((t & 31) == 0) sh[t >> 5] = wsum;
    __syncthreads();
    float sum = 0.f;
    #pragma unroll
    for (int w = 0; w < 8; w++) sum += sh[w];
    const float sinv = 1.f / sum;

    __half* ph = g_ph + rowoff;
    #pragma unroll
    for (int q = 0; q < 8; q++){
        const int j = q*256 + t;
        ph[j] = __float2half_rn(sv[q] * sinv);
    }
}

// ---------------- kernel 4: fp16 PV GEMM (K-chunk 64) ----------------
#define PV_BUF   27648
#define PV_SMEM  55296

__global__ __launch_bounds__(256) void pv_mma_kernel(int bh0)
{
    extern __shared__ __align__(128) char smem[];
    const uint32_t sbase = smem_u32(smem);
    const int tid = threadIdx.x, lane = tid & 31, wid = tid >> 5;
    const int bh = bh0 + blockIdx.y;
    const int i0 = blockIdx.x * 128;
    const __half* Pp = g_ph + (size_t)bh*SEQ*TT + (size_t)i0*TT;
    const __half* Vp = g_v + (size_t)bh*TT*DH;

    const int wm = (wid & 3) * 32;
    const int wn = (wid >> 2) * 32;
    const int lsel = lane & 15;
    const int kof  = (lane < 16) ? 0 : 8;
    const int tcol = (lane >> 4) * 8;

    float acc[2][4][4];
    #pragma unroll
    for (int mt = 0; mt < 2; mt++)
        #pragma unroll
        for (int nt = 0; nt < 4; nt++)
            #pragma unroll
            for (int q = 0; q < 4; q++) acc[mt][nt][q] = 0.f;

    auto issue = [&](int c, int b){
        const int k0 = c * 64;
        const uint32_t sb = sbase + b * PV_BUF;
        #pragma unroll
        for (int p = 0; p < 4; p++){
            const int u = p * 256 + tid;
            const int row = u >> 3, seg = u & 7;
            cp16(sb + row * 144 + seg * 16, Pp + (size_t)row * TT + k0 + seg * 8);
        }
        #pragma unroll
        for (int p = 0; p < 2; p++){
            const int u = p * 256 + tid;
            const int row = u >> 3, seg = u & 7;
            cp16(sb + 18432 + row * 144 + seg * 16, Vp + (size_t)(k0 + row) * DH + seg * 8);
        }
        CP_COMMIT();
    };

    issue(0, 0);
    for (int c = 0; c < 32; c++){
        CP_WAIT0();
        __syncthreads();
        if (c + 1 < 32) issue(c + 1, (c + 1) & 1);
        const uint32_t sb = sbase + (c & 1) * PV_BUF;
        #pragma unroll
        for (int kk = 0; kk < 64; kk += 16){
            uint32_t ph[2][4], vh[2][4];
            #pragma unroll
            for (int mt = 0; mt < 2; mt++)
                ldm4(ph[mt], sb + (wm + mt*16 + lsel) * 144 + (kk + kof) * 2);
            #pragma unroll
            for (int g = 0; g < 2; g++)
                ldm4t(vh[g], sb + 18432 + (kk + lsel) * 144 + (wn + g*16 + tcol) * 2);
            #pragma unroll
            for (int mt = 0; mt < 2; mt++)
                #pragma unroll
                for (int nt = 0; nt < 4; nt++){
                    const int g = nt >> 1, s = nt & 1;
                    mma_f16(acc[mt][nt], ph[mt], vh[g][2*s], vh[g][2*s+1]);
                }
        }
    }

    __syncthreads();
    float* stg = (float*)smem;
    const int fr = lane >> 2, fc = (lane & 3) * 2;
    #pragma unroll
    for (int mt = 0; mt < 2; mt++)
        #pragma unroll
        for (int nt = 0; nt < 4; nt++){
            const int col = wn + nt*8 + fc;
            const int row0 = wm + mt*16 + fr;
            stg[row0*68 + col]       = acc[mt][nt][0];
            stg[row0*68 + col + 1]   = acc[mt][nt][1];
            stg[(row0+8)*68 + col]   = acc[mt][nt][2];
            stg[(row0+8)*68 + col+1] = acc[mt][nt][3];
        }
    __syncthreads();
    const int rr = tid >> 1, hf = tid & 1;
    const int b = bh >> 4, h = bh & 15;
    const int i = i0 + rr;
    const float* src = stg + rr * 68 + hf * 32;
    const size_t off = ((size_t)i*BATCH + b)*DM + h*DH + hf*32;
    #pragma unroll
    for (int s = 0; s < 4; s++)
        *(uint4*)(g_av + off + s*8) = pack8h(src + s*8);
}

// ---------------- kernel 5: fp16 out projection + residual (K-chunk 64) ----------------
#define OP_BUF   36864
#define OP_SMEM  73728

__global__ __launch_bounds__(256) void outproj_mma_kernel(const float* __restrict__ x,
                                                          float* __restrict__ out)
{
    extern __shared__ __align__(128) char smem[];
    const uint32_t sbase = smem_u32(smem);
    const int tid = threadIdx.x, lane = tid & 31, wid = tid >> 5;
    const int n0 = blockIdx.x * 128;
    const int m0 = blockIdx.y * 128;
    const __half* Ap = g_av + (size_t)m0 * 1024;
    const __half* Bp = g_wo + (size_t)n0 * 1024;

    const int wm = (wid & 3) * 32;
    const int wn = (wid >> 2) * 64;
    const int lsel = lane & 15;
    const int kof  = (lane < 16) ? 0 : 8;

    float acc[2][8][4];
    #pragma unroll
    for (int mt = 0; mt < 2; mt++)
        #pragma unroll
        for (int nt = 0; nt < 8; nt++)
            #pragma unroll
            for (int q = 0; q < 4; q++) acc[mt][nt][q] = 0.f;

    auto issue = [&](int c, int b){
        const int k0 = c * 64;
        const uint32_t sb = sbase + b * OP_BUF;
        #pragma unroll
        for (int p = 0; p < 4; p++){
            const int u = p * 256 + tid;
            const int row = u >> 3, seg = u & 7;
            const size_t go = (size_t)row * 1024 + k0 + seg * 8;
            const uint32_t so = row * 144 + seg * 16;
            cp16(sb + so,         Ap + go);
            cp16(sb + 18432 + so, Bp + go);
        }
        CP_COMMIT();
    };

    issue(0, 0);
    for (int c = 0; c < 16; c++){
        CP_WAIT0();
        __syncthreads();
        if (c + 1 < 16) issue(c + 1, (c + 1) & 1);
        const uint32_t sb = sbase + (c & 1) * OP_BUF;
        #pragma unroll
        for (int kk = 0; kk < 64; kk += 16){
            uint32_t ah[2][4], bh[4][4];
            #pragma unroll
            for (int mt = 0; mt < 2; mt++)
                ldm4(ah[mt], sb + (wm + mt*16 + lsel) * 144 + (kk + kof) * 2);
            #pragma unroll
            for (int g = 0; g < 4; g++)
                ldm4(bh[g], sb + 18432 + (wn + g*16 + lsel) * 144 + (kk + kof) * 2);
            #pragma unroll
            for (int mt = 0; mt < 2; mt++)
                #pragma unroll
                for (int nt = 0; nt < 8; nt++){
                    const int g = nt >> 1, s = nt & 1;
                    mma_f16(acc[mt][nt], ah[mt], bh[g][s], bh[g][s+2]);
                }
        }
    }

    __syncthreads();
    float* stg = (float*)smem;
    const int fr = lane >> 2, fc = (lane & 3) * 2;
    #pragma unroll
    for (int mt = 0; mt < 2; mt++)
        #pragma unroll
        for (int nt = 0; nt < 8; nt++){
            const int col = wn + nt*8 + fc;
            const int row0 = wm + mt*16 + fr;
            stg[row0*132 + col]       = acc[mt][nt][0];
            stg[row0*132 + col + 1]   = acc[mt][nt][1];
            stg[(row0+8)*132 + col]   = acc[mt][nt][2];
            stg[(row0+8)*132 + col+1] = acc[mt][nt][3];
        }
    __syncthreads();
    const int rr = tid >> 1, hf = tid & 1;
    const int m = m0 + rr;
    const float* src = stg + rr * 132 + hf * 64;
    const float* xr = x + (size_t)m*DM + n0 + hf*64;
    float* orow = out + (size_t)m*DM + n0 + hf*64;
    #pragma unroll
    for (int s = 0; s < 16; s++){
        float4 v = *(const float4*)(src + s*4);
        float4 xx = *(const float4*)(xr + s*4);
        *(float4*)(orow + s*4) = make_float4(v.x+xx.x, v.y+xx.y, v.z+xx.z, v.w+xx.w);
    }
}

// ---------------- kernel 6: LayerNorm ----------------
__global__ __launch_bounds__(256) void ln_kernel(float* __restrict__ out,
                                                 const float* __restrict__ gamma,
                                                 const float* __restrict__ beta)
{
    const int row = blockIdx.x;
    float* y = out + (size_t)row * DM;
    const int t = threadIdx.x;
    float v[4];
    float s = 0.f, sq = 0.f;
    #pragma unroll
    for (int q = 0; q < 4; q++){
        v[q] = y[q*256 + t];
        s += v[q];
        sq += v[q]*v[q];
    }
    __shared__ float sh[16];
    float ws = warpReduceSum(s);
    float wq = warpReduceSum(sq);
    if ((t & 31) == 0){ sh[t>>5] = ws; sh[8 + (t>>5)] = wq; }
    __syncthreads();
    s = 0.f; sq = 0.f;
    #pragma unroll
    for (int w = 0; w < 8; w++){ s += sh[w]; sq += sh[8+w]; }
    const float mu = s * (1.f/1024.f);
    const float var = sq * (1.f/1024.f) - mu*mu;
    const float rstd = rsqrtf(var + 1e-5f);
    #pragma unroll
    for (int q = 0; q < 4; q++){
        const int d = q*256 + t;
        y[d] = gamma[d] * ((v[q] - mu) * rstd) + beta[d];
    }
}

// ---------------- launch ----------------
#define NCHUNK 4
#define CHBH   16

extern "C" void kernel_launch(void* const* d_in, const int* in_sizes, int n_in,
                              void* d_out, int out_size)
{
    const float* x     = (const float*)d_in[0];
    const float* mem   = (const float*)d_in[1];
    const float* pos   = (const float*)d_in[2];
    const float* pbu   = (const float*)d_in[3];
    const float* pbv   = (const float*)d_in[4];
    const float* Wqkv  = (const float*)d_in[5];
    const float* Wrel  = (const float*)d_in[6];
    const float* Wo    = (const float*)d_in[7];
    const float* gamma = (const float*)d_in[8];
    const float* beta  = (const float*)d_in[9];
    float* out = (float*)d_out;

    static cudaStream_t s1 = nullptr;
    static cudaEvent_t evS[NCHUNK], evM[NCHUNK];
    if (!s1){
        cudaStreamCreateWithFlags(&s1, cudaStreamNonBlocking);
        for (int c = 0; c < NCHUNK; c++){
            cudaEventCreateWithFlags(&evS[c], cudaEventDisableTiming);
            cudaEventCreateWithFlags(&evM[c], cudaEventDisableTiming);
        }
        cudaFuncSetAttribute(proj_mma_kernel,    cudaFuncAttributeMaxDynamicSharedMemorySize, PJ_SMEM);
        cudaFuncSetAttribute(score_mma_kernel,   cudaFuncAttributeMaxDynamicSharedMemorySize, SC_SMEM);
        cudaFuncSetAttribute(pv_mma_kernel,      cudaFuncAttributeMaxDynamicSharedMemorySize, PV_SMEM);
        cudaFuncSetAttribute(outproj_mma_kernel, cudaFuncAttributeMaxDynamicSharedMemorySize, OP_SMEM);
    }

    conv_kernel<<<21504, 256>>>(x, mem, pos, Wqkv, Wrel, Wo);
    proj_mma_kernel<<<1792, 256, PJ_SMEM>>>(pbu, pbv);

    for (int c = 0; c < NCHUNK; c++){
        score_mma_kernel<<<dim3(2, 8, 2*CHBH), 256, SC_SMEM>>>(c * CHBH);
        cudaEventRecord(evS[c], 0);
        cudaStreamWaitEvent(s1, evS[c], 0);
        softmax_shift_kernel<<<dim3(1024, CHBH), 256, 0, s1>>>(c * CHBH);
        cudaEventRecord(evM[c], s1);
    }
    cudaStreamWaitEvent(0, evM[0], 0);
    cudaStreamWaitEvent(0, evM[1], 0);
    cudaStreamWaitEvent(0, evM[2], 0);
    pv_mma_kernel<<<dim3(8, 48), 256, PV_SMEM>>>(0);
    cudaStreamWaitEvent(0, evM[3], 0);
    pv_mma_kernel<<<dim3(8, 16), 256, PV_SMEM>>>(48);

    outproj_mma_kernel<<<dim3(8, 32), 256, OP_SMEM>>>(x, out);
    ln_kernel<<<4096, 256>>>(out, gamma, beta);
}